// round 10
// baseline (speedup 1.0000x reference)
#include <cuda_runtime.h>
#include <cstdint>

typedef unsigned long long u64;
#define NT 512

// ---------------- scratch (no allocations allowed) ----------------
struct Scratch {
    float yr[16 * 512];          // fa_r output rows
    float rc[3][16 * 256];       // precomputed updated r per read-slot
    float updw[48];              // sigmoid update weights [b*3+i]
    u64 pack[48];                // (orderable_max << 32 | ~idx)
};
__device__ Scratch g_s;

__device__ __forceinline__ unsigned forder(float f) {
    unsigned u = __float_as_uint(f);
    return (u & 0x80000000u) ? ~u : (u | 0x80000000u);
}
__device__ __forceinline__ float forder_inv(unsigned u) {
    unsigned v = (u & 0x80000000u) ? (u & 0x7FFFFFFFu) : ~u;
    return __uint_as_float(v);
}
__device__ __forceinline__ u64 pack2(float f) {
    unsigned u = __float_as_uint(f);
    return ((u64)u << 32) | (u64)u;
}
__device__ __forceinline__ u64 packf2(float lo, float hi) {
    return ((u64)__float_as_uint(hi) << 32) | (u64)__float_as_uint(lo);
}
__device__ __forceinline__ void ffma2(u64& acc, u64 x, u64 w) {
    asm("fma.rn.f32x2 %0, %1, %2, %0;" : "+l"(acc) : "l"(x), "l"(w));
}
__device__ __forceinline__ u64 addf2(u64 a, u64 b) {
    u64 d;
    asm("add.rn.f32x2 %0, %1, %2;" : "=l"(d) : "l"(a), "l"(b));
    return d;
}
__device__ __forceinline__ float lohi(u64 v, int hi) {
    return __uint_as_float(hi ? (unsigned)(v >> 32) : (unsigned)v);
}

// ---------- block GEMM: xs2 [k][P] packed pairs; W [K x N]; float4 W loads ----------
// Warp grid: NJW warps across j (128 j each), NK k-slices. Own threads (ks==0,
// warp<NJW) return full dot for columns j..j+3 in a[P][4].
template <int P, int NJW, int NK, int K, int N>
__device__ __forceinline__ bool bgemm(const u64* __restrict__ xs2,
                                      const float* __restrict__ W,
                                      u64 (&a)[P][4], u64* part, int& jout) {
    const int tid = threadIdx.x, w = tid >> 5, lane = tid & 31;
    const int jt = w % NJW, ks = w / NJW;
    const bool act = w < NJW * NK;
    jout = jt * 128 + lane * 4;
    constexpr int KC = K / NK;
    __syncthreads();   // protects part + input buffers from previous stage
    #pragma unroll
    for (int p = 0; p < P; p++)
        #pragma unroll
        for (int q = 0; q < 4; q++) a[p][q] = 0ull;
    if (act) {
        const float* wp = W + (long)(ks * KC) * N + jout;
        const u64* xk = xs2 + ks * KC * P;
        #pragma unroll 4
        for (int t = 0; t < KC; t++) {
            float4 wv = __ldg((const float4*)wp);
            u64 w0 = pack2(wv.x), w1 = pack2(wv.y), w2 = pack2(wv.z), w3 = pack2(wv.w);
            #pragma unroll
            for (int p = 0; p < P; p++) {
                u64 xv = xk[p];
                ffma2(a[p][0], xv, w0);
                ffma2(a[p][1], xv, w1);
                ffma2(a[p][2], xv, w2);
                ffma2(a[p][3], xv, w3);
            }
            wp += N; xk += P;
        }
        if (ks > 0) {
            u64* ps = part + (((ks - 1) * NJW + jt) * 32 + lane) * (P * 4);
            #pragma unroll
            for (int p = 0; p < P; p++)
                #pragma unroll
                for (int q = 0; q < 4; q++) ps[p * 4 + q] = a[p][q];
        }
    }
    __syncthreads();
    if (act && ks == 0) {
        #pragma unroll
        for (int h = 0; h < NK - 1; h++) {
            const u64* ps = part + ((h * NJW + jt) * 32 + lane) * (P * 4);
            #pragma unroll
            for (int p = 0; p < P; p++)
                #pragma unroll
                for (int q = 0; q < 4; q++) a[p][q] = addf2(a[p][q], ps[p * 4 + q]);
        }
    }
    return act && (ks == 0);
}

// exp epilogue (linearized softmax): store exp(v+b) packed into xh, compute
// per-row inverse sums into sinv[2P]. red must hold NJW*2*P floats.
template <int P, int NJW>
__device__ __forceinline__ void epi_exp(bool own, u64 (&a)[P][4], int j,
                                        const float* __restrict__ bias,
                                        u64* xh, float* red, float* sinv) {
    const int w = threadIdx.x >> 5, lane = threadIdx.x & 31;
    if (own) {
        float4 bv = __ldg((const float4*)(bias + j));
        float bq[4] = {bv.x, bv.y, bv.z, bv.w};
        float sl[P], sh2[P];
        #pragma unroll
        for (int p = 0; p < P; p++) { sl[p] = 0.f; sh2[p] = 0.f; }
        #pragma unroll
        for (int q = 0; q < 4; q++)
            #pragma unroll
            for (int p = 0; p < P; p++) {
                float lo = __expf(lohi(a[p][q], 0) + bq[q]);
                float hi = __expf(lohi(a[p][q], 1) + bq[q]);
                xh[(j + q) * P + p] = packf2(lo, hi);
                sl[p] += lo; sh2[p] += hi;
            }
        #pragma unroll
        for (int p = 0; p < P; p++) {
            #pragma unroll
            for (int o = 16; o; o >>= 1) {
                sl[p] += __shfl_xor_sync(0xffffffffu, sl[p], o);
                sh2[p] += __shfl_xor_sync(0xffffffffu, sh2[p], o);
            }
        }
        if (lane == 0) {
            #pragma unroll
            for (int p = 0; p < P; p++) {
                red[w * 2 * P + 2 * p] = sl[p];
                red[w * 2 * P + 2 * p + 1] = sh2[p];
            }
        }
    }
    __syncthreads();
    if (threadIdx.x < 2 * P) {
        float s = 0.f;
        #pragma unroll
        for (int h = 0; h < NJW; h++) s += red[h * 2 * P + (int)threadIdx.x];
        sinv[threadIdx.x] = 1.f / s;
    }
    __syncthreads();
}

// ================= K0: full fa_r / fa_u per 2-row block + updw + pack init =========
__global__ void __launch_bounds__(NT, 1) k0(
    const float* __restrict__ inputs,
    const float* __restrict__ r_w1, const float* __restrict__ r_b1,
    const float* __restrict__ r_w2, const float* __restrict__ r_b2,
    const float* __restrict__ u_w1, const float* __restrict__ u_b1,
    const float* __restrict__ u_w2, const float* __restrict__ u_b2,
    const float* __restrict__ W_uw, const float* __restrict__ b_uw) {
    extern __shared__ u64 sh[];
    const int tid = threadIdx.x, bx = blockIdx.x;
    if (bx == 16) {
        if (tid < 48) g_s.pack[tid] = 0ull;
        return;
    }
    u64* xs_in = sh;                 // 512
    u64* xsh = sh + 512;             // 512
    u64* part = sh + 1024;           // 1536
    float* red = (float*)(sh + 2560);   // 8 floats (4 u64)
    float* sinv = (float*)(sh + 2564);  // 2 floats

    const int fu = bx >> 3;          // 0 = fa_r, 1 = fa_u
    const int r0 = (bx & 7) * 2;     // rows r0, r0+1

    xs_in[tid] = packf2(__ldg(inputs + r0 * 512 + tid),
                        __ldg(inputs + (r0 + 1) * 512 + tid));
    u64 a[1][4]; int j;
    bool own = bgemm<1, 4, 4, 512, 512>(xs_in, fu ? u_w1 : r_w1, a, part, j);
    epi_exp<1, 4>(own, a, j, fu ? u_b1 : r_b1, xsh, red, sinv);
    own = bgemm<1, 4, 4, 512, 512>(xsh, fu ? u_w2 : r_w2, a, part, j);
    if (own) {
        float4 bv = __ldg((const float4*)((fu ? u_b2 : r_b2) + j));
        float bq[4] = {bv.x, bv.y, bv.z, bv.w};
        #pragma unroll
        for (int q = 0; q < 4; q++) {
            float vlo = lohi(a[0][q], 0) * sinv[0] + bq[q];
            float vhi = lohi(a[0][q], 1) * sinv[1] + bq[q];
            u64 xv = xs_in[j + q];
            float ylo = lohi(xv, 0) * vlo, yhi = lohi(xv, 1) * vhi;
            if (fu == 0) {
                g_s.yr[r0 * 512 + j + q] = ylo;
                g_s.yr[(r0 + 1) * 512 + j + q] = yhi;
            } else {
                xsh[j + q] = packf2(ylo, yhi);
            }
        }
    }
    if (fu == 1) {
        __syncthreads();
        const int w = tid >> 5, lane = tid & 31;
        if (w < 3) {
            u64 acc = 0ull;
            for (int k = lane; k < 512; k += 32)
                ffma2(acc, xsh[k], pack2(__ldg(W_uw + k * 3 + w)));
            #pragma unroll
            for (int o = 16; o; o >>= 1)
                acc = addf2(acc, __shfl_xor_sync(0xffffffffu, acc, o));
            if (lane == 0) {
                float bb = __ldg(b_uw + w);
                g_s.updw[r0 * 3 + w] = 1.f / (1.f + __expf(-(lohi(acc, 0) + bb)));
                g_s.updw[(r0 + 1) * 3 + w] = 1.f / (1.f + __expf(-(lohi(acc, 1) + bb)));
            }
        }
    }
}

// ================= K1: big read GEMM + fused max/argmax =================
__global__ void __launch_bounds__(NT, 1) k1(const float* __restrict__ W,
                                            const float* __restrict__ bias) {
    extern __shared__ u64 shr[];
    u64* xs2 = shr;              // [k][pair] 512*8
    u64* part = shr + 4096;      // 4 slots * 3 * 32 * 16
    const int tid = threadIdx.x, bx = blockIdx.x;
    const int NB = gridDim.x;

    for (int idx = tid; idx < 4096; idx += NT) {
        int p = idx / 512, k = idx - p * 512;
        float lo = __ldcg(g_s.yr + (2 * p) * 512 + k);
        float hi = __ldcg(g_s.yr + (2 * p + 1) * 512 + k);
        xs2[k * 8 + p] = packf2(lo, hi);
    }
    __syncthreads();

    const int w = tid >> 5, lane = tid & 31;
    const int ts = w >> 2, kh = w & 3;
    const int base = 471 / NB, rem = 471 - base * NB;
    const int cnt = base + (bx < rem ? 1 : 0);
    const int start = bx * base + (bx < rem ? bx : rem);
    const bool act = ts < cnt;

    int isec = 0, j0 = 0, j1 = 0;
    long n0 = 0;
    bool v0 = false;
    u64 a0[8], a1[8];

    if (act) {
        int gtile = start + ts;
        isec = gtile / 157;
        int t = gtile - isec * 157;
        j0 = t * 64 + lane * 2; j1 = j0 + 1;
        v0 = j0 < 10000;
        n0 = (long)isec * 10000 + j0;
        #pragma unroll
        for (int p = 0; p < 8; p++) { a0[p] = 0ull; a1[p] = 0ull; }

        const float* W0 = W + (long)(kh * 128) * 30000;
        const u64* xk = xs2 + (kh * 128) * 8;
        #pragma unroll 4
        for (int it = 0; it < 128; it++) {
            float2 wv = v0 ? __ldg((const float2*)(W0 + n0)) : make_float2(0.f, 0.f);
            u64 wa2 = pack2(wv.x), wb2 = pack2(wv.y);
            #pragma unroll
            for (int p = 0; p < 8; p++) {
                u64 xv = xk[p];
                ffma2(a0[p], xv, wa2);
                ffma2(a1[p], xv, wb2);
            }
            W0 += 30000; xk += 8;
        }
        if (kh > 0) {
            u64* ps = part + ((ts * 3 + (kh - 1)) * 32 + lane) * 16;
            #pragma unroll
            for (int p = 0; p < 8; p++) { ps[p] = a0[p]; ps[8 + p] = a1[p]; }
        }
    }
    __syncthreads();

    if (act && kh == 0) {
        #pragma unroll
        for (int h = 0; h < 3; h++) {
            const u64* ps = part + ((ts * 3 + h) * 32 + lane) * 16;
            #pragma unroll
            for (int p = 0; p < 8; p++) {
                a0[p] = addf2(a0[p], ps[p]);
                a1[p] = addf2(a1[p], ps[8 + p]);
            }
        }
        float2 bv = v0 ? __ldg((const float2*)(bias + n0)) : make_float2(0.f, 0.f);
        #pragma unroll
        for (int b = 0; b < 16; b++) {
            float z0 = lohi(a0[b >> 1], b & 1) + bv.x;
            float z1 = lohi(a1[b >> 1], b & 1) + bv.y;
            u64 c0 = v0 ? (((u64)forder(z0) << 32) | (u64)(0xFFFFFFFFu - (unsigned)j0)) : 0ull;
            u64 c1 = v0 ? (((u64)forder(z1) << 32) | (u64)(0xFFFFFFFFu - (unsigned)j1)) : 0ull;
            u64 c = c0 > c1 ? c0 : c1;
            #pragma unroll
            for (int o = 16; o; o >>= 1) {
                u64 q = __shfl_xor_sync(0xffffffffu, c, o);
                if (q > c) c = q;
            }
            if (lane == 0) atomicMax(&g_s.pack[b * 3 + isec], c);
        }
    }
}

// ================= K2: fa_um (both stages) + r-update, per (i, 4 rows) ============
__global__ void __launch_bounds__(NT, 1) k2(
    const float* __restrict__ inputs, const float* __restrict__ memory,
    const float* __restrict__ um_w1, const float* __restrict__ um_b1,
    const float* __restrict__ um_w2, const float* __restrict__ um_b2,
    const float* __restrict__ W_um, const float* __restrict__ b_um) {
    extern __shared__ u64 sh[];
    u64* xs_cat = sh;                // 1536 (768 x 2 pairs)
    u64* xsh = sh + 1536;            // 1536
    u64* part = sh + 3072;           // 1536
    float* red = (float*)(sh + 4608);   // 24 floats (12 u64)
    float* sinv = (float*)(sh + 4620);  // 4 floats (2 u64)
    __shared__ long rowoff[4];
    __shared__ float su[4];

    const int tid = threadIdx.x, bx = blockIdx.x;
    const int i = bx >> 2, bq = bx & 3;
    const int r0 = bq * 4;           // rows r0..r0+3

    if (tid < 4) {
        u64 p = __ldcg(&g_s.pack[(r0 + tid) * 3 + i]);
        unsigned idx = 0xFFFFFFFFu - (unsigned)(p & 0xFFFFFFFFull);
        rowoff[tid] = ((long)(r0 + tid) * 10000 + idx) * 256;
        su[tid] = __ldcg(&g_s.updw[(r0 + tid) * 3 + i]);
    }
    __syncthreads();
    for (int idx = tid; idx < 1536; idx += NT) {
        int p = idx & 1, k = idx >> 1;
        float lo, hi;
        if (k < 256) {
            lo = __ldg(memory + rowoff[2 * p] + k);
            hi = __ldg(memory + rowoff[2 * p + 1] + k);
        } else {
            lo = __ldg(inputs + (r0 + 2 * p) * 512 + (k - 256));
            hi = __ldg(inputs + (r0 + 2 * p + 1) * 512 + (k - 256));
        }
        xs_cat[k * 2 + p] = packf2(lo, hi);
    }
    u64 a[2][4]; int j;
    bool own = bgemm<2, 6, 2, 768, 768>(xs_cat, um_w1, a, part, j);
    epi_exp<2, 6>(own, a, j, um_b1, xsh, red, sinv);
    own = bgemm<2, 6, 2, 768, 768>(xsh, um_w2, a, part, j);
    if (own) {
        float4 bv = __ldg((const float4*)(um_b2 + j));
        float bq4[4] = {bv.x, bv.y, bv.z, bv.w};
        #pragma unroll
        for (int q = 0; q < 4; q++)
            #pragma unroll
            for (int p = 0; p < 2; p++) {
                float vlo = lohi(a[p][q], 0) * sinv[2 * p] + bq4[q];
                float vhi = lohi(a[p][q], 1) * sinv[2 * p + 1] + bq4[q];
                u64 cv = xs_cat[(j + q) * 2 + p];
                xsh[(j + q) * 2 + p] = packf2(lohi(cv, 0) * vlo, lohi(cv, 1) * vhi);
            }
    }
    // r update: rc = u*relu(yum@W_um + b) + (1-u)*r
    own = bgemm<2, 2, 4, 768, 256>(xsh, W_um, a, part, j);
    if (own) {
        float4 bv = __ldg((const float4*)(b_um + j));
        float bq4[4] = {bv.x, bv.y, bv.z, bv.w};
        #pragma unroll
        for (int q = 0; q < 4; q++)
            #pragma unroll
            for (int p = 0; p < 2; p++) {
                float vlo = fmaxf(lohi(a[p][q], 0) + bq4[q], 0.f);
                float vhi = fmaxf(lohi(a[p][q], 1) + bq4[q], 0.f);
                u64 rv = xs_cat[(j + q) * 2 + p];
                float ulo = su[2 * p], uhi = su[2 * p + 1];
                g_s.rc[i][(r0 + 2 * p) * 256 + j + q] =
                    ulo * vlo + (1.f - ulo) * lohi(rv, 0);
                g_s.rc[i][(r0 + 2 * p + 1) * 256 + j + q] =
                    uhi * vhi + (1.f - uhi) * lohi(rv, 1);
            }
    }
}

// ================= K3: full recurrent loop, 2 rows per block =================
__global__ void __launch_bounds__(NT, 1) k3(
    const float* __restrict__ am_w1, const float* __restrict__ am_b1,
    const float* __restrict__ am_w2, const float* __restrict__ am_b2,
    const float* __restrict__ W_am, const float* __restrict__ b_am,
    float* __restrict__ out) {
    extern __shared__ u64 sh[];
    u64* xs_c2 = sh;                 // 512: [rc(256) | m(256)]
    u64* xsh = sh + 512;             // 512
    u64* part = sh + 1024;           // 1536
    float* red = (float*)(sh + 2560);   // 8 floats
    float* sinv = (float*)(sh + 2564);  // 2 floats
    __shared__ float srw[6];         // [rr*3+i]

    const int tid = threadIdx.x;
    const int r0 = blockIdx.x * 2;

    if (tid < 6) {
        int rr = tid / 3, ii = tid - rr * 3;
        u64 p = __ldcg(&g_s.pack[(r0 + rr) * 3 + ii]);
        srw[tid] = tanhf(forder_inv((unsigned)(p >> 32)));
    }
    __syncthreads();

    u64 a[1][4]; int j;
    for (int i = 0; i < 3; i++) {
        if (tid < 256)
            xs_c2[tid] = packf2(__ldcg(g_s.rc[i] + r0 * 256 + tid),
                                __ldcg(g_s.rc[i] + (r0 + 1) * 256 + tid));
        else if (i == 0)
            xs_c2[tid] = 0ull;
        bool own = bgemm<1, 4, 4, 512, 512>(xs_c2, am_w1, a, part, j);
        epi_exp<1, 4>(own, a, j, am_b1, xsh, red, sinv);
        own = bgemm<1, 4, 4, 512, 512>(xsh, am_w2, a, part, j);
        if (own) {
            float4 bv = __ldg((const float4*)(am_b2 + j));
            float bq4[4] = {bv.x, bv.y, bv.z, bv.w};
            #pragma unroll
            for (int q = 0; q < 4; q++) {
                float vlo = lohi(a[0][q], 0) * sinv[0] + bq4[q];
                float vhi = lohi(a[0][q], 1) * sinv[1] + bq4[q];
                u64 cv = xs_c2[j + q];
                xsh[j + q] = packf2(lohi(cv, 0) * vlo, lohi(cv, 1) * vhi);
            }
        }
        own = bgemm<1, 2, 4, 512, 256>(xsh, W_am, a, part, j);
        if (own) {
            float4 bv = __ldg((const float4*)(b_am + j));
            float bq4[4] = {bv.x, bv.y, bv.z, bv.w};
            float rwlo = srw[i], rwhi = srw[3 + i];
            #pragma unroll
            for (int q = 0; q < 4; q++) {
                float mlo = rwlo * fmaxf(lohi(a[0][q], 0) + bq4[q], 0.f);
                float mhi = rwhi * fmaxf(lohi(a[0][q], 1) + bq4[q], 0.f);
                xs_c2[256 + j + q] = packf2(mlo, mhi);
                if (i == 2) {
                    out[r0 * 256 + j + q] = tanhf(mlo);
                    out[(r0 + 1) * 256 + j + q] = tanhf(mhi);
                }
            }
        }
        __syncthreads();
    }
}

// ---------------- host launcher ----------------
extern "C" void kernel_launch(void* const* d_in, const int* in_sizes, int n_in,
                              void* d_out, int out_size) {
    const float* inputs = (const float*)d_in[0];
    const float* memory = (const float*)d_in[1];
    const float* r_w1 = (const float*)d_in[2];
    const float* r_b1 = (const float*)d_in[3];
    const float* r_w2 = (const float*)d_in[4];
    const float* r_b2 = (const float*)d_in[5];
    const float* W_read = (const float*)d_in[6];
    const float* b_read = (const float*)d_in[7];
    const float* u_w1 = (const float*)d_in[8];
    const float* u_b1 = (const float*)d_in[9];
    const float* u_w2 = (const float*)d_in[10];
    const float* u_b2 = (const float*)d_in[11];
    const float* W_uw = (const float*)d_in[12];
    const float* b_uw = (const float*)d_in[13];
    const float* um_w1 = (const float*)d_in[14];
    const float* um_b1 = (const float*)d_in[15];
    const float* um_w2 = (const float*)d_in[16];
    const float* um_b2 = (const float*)d_in[17];
    const float* W_um = (const float*)d_in[18];
    const float* b_um = (const float*)d_in[19];
    const float* am_w1 = (const float*)d_in[20];
    const float* am_b1 = (const float*)d_in[21];
    const float* am_w2 = (const float*)d_in[22];
    const float* am_b2 = (const float*)d_in[23];
    const float* W_am = (const float*)d_in[24];
    const float* b_am = (const float*)d_in[25];
    float* out = (float*)d_out;

    static int NB = 0;
    if (NB == 0) {
        cudaDeviceGetAttribute(&NB, cudaDevAttrMultiProcessorCount, 0);
        if (NB <= 0) NB = 148;
    }
    const int DSM0 = 20608;   // k0/k3: 2576 u64
    const int DSM1 = 81920;   // k1
    const int DSM2 = 36976;   // k2: 4622 u64 (red 12 + sinv 2 after part)
    static bool attr_set = false;
    if (!attr_set) {
        cudaFuncSetAttribute(k0, cudaFuncAttributeMaxDynamicSharedMemorySize, DSM0);
        cudaFuncSetAttribute(k1, cudaFuncAttributeMaxDynamicSharedMemorySize, DSM1);
        cudaFuncSetAttribute(k2, cudaFuncAttributeMaxDynamicSharedMemorySize, DSM2);
        cudaFuncSetAttribute(k3, cudaFuncAttributeMaxDynamicSharedMemorySize, DSM0);
        attr_set = true;
    }

    k0<<<17, NT, DSM0>>>(inputs, r_w1, r_b1, r_w2, r_b2,
                         u_w1, u_b1, u_w2, u_b2, W_uw, b_uw);
    k1<<<NB, NT, DSM1>>>(W_read, b_read);
    k2<<<12, NT, DSM2>>>(inputs, memory, um_w1, um_b1, um_w2, um_b2, W_um, b_um);
    k3<<<8, NT, DSM0>>>(am_w1, am_b1, am_w2, am_b2, W_am, b_am, out);
}

// round 11
// speedup vs baseline: 2.2105x; 2.2105x over previous
#include <cuda_runtime.h>
#include <cstdint>

typedef unsigned long long u64;

// ---------------- scratch (no allocations allowed) ----------------
struct Scratch {
    float yr[16 * 512];          // fa_r output rows
    float rc[3][16 * 256];       // precomputed updated r per read-slot
    float updw[48];              // sigmoid update weights [b*3+i]
    u64 pack[48];                // (orderable_max << 32 | ~idx)
};
__device__ Scratch g_s;

__device__ __forceinline__ unsigned forder(float f) {
    unsigned u = __float_as_uint(f);
    return (u & 0x80000000u) ? ~u : (u | 0x80000000u);
}
__device__ __forceinline__ float forder_inv(unsigned u) {
    unsigned v = (u & 0x80000000u) ? (u & 0x7FFFFFFFu) : ~u;
    return __uint_as_float(v);
}
__device__ __forceinline__ u64 pack2(float f) {
    unsigned u = __float_as_uint(f);
    return ((u64)u << 32) | (u64)u;
}
__device__ __forceinline__ u64 packf2(float lo, float hi) {
    return ((u64)__float_as_uint(hi) << 32) | (u64)__float_as_uint(lo);
}
__device__ __forceinline__ void ffma2(u64& acc, u64 x, u64 w) {
    asm("fma.rn.f32x2 %0, %1, %2, %0;" : "+l"(acc) : "l"(x), "l"(w));
}
__device__ __forceinline__ u64 addf2(u64 a, u64 b) {
    u64 d;
    asm("add.rn.f32x2 %0, %1, %2;" : "=l"(d) : "l"(a), "l"(b));
    return d;
}
__device__ __forceinline__ float lohi(u64 v, int hi) {
    return __uint_as_float(hi ? (unsigned)(v >> 32) : (unsigned)v);
}

// ---------- block GEMM (row-pair packed): N<=NJW*128 cols, NK k-slices ----------
// xs2[k]: packed pair for k. Warp (jt, ks): jt covers j = jt*128 + lane*4..+3.
// D = explicit prefetch depth (independent LDG.128s in flight).
template <int NJW, int NK, int K, int N, int D>
__device__ __forceinline__ bool bgemm(const u64* __restrict__ xs2,
                                      const float* __restrict__ W,
                                      u64 (&a)[4], u64* part, int& jout) {
    const int tid = threadIdx.x, w = tid >> 5, lane = tid & 31;
    const int jt = w % NJW, ks = w / NJW;
    const bool act = w < NJW * NK;
    jout = jt * 128 + lane * 4;
    constexpr int KC = K / NK;
    __syncthreads();   // protects part + input buffers from previous stage
    #pragma unroll
    for (int q = 0; q < 4; q++) a[q] = 0ull;
    if (act) {
        const float* wp = W + (long)(ks * KC) * N + jout;
        const u64* xk = xs2 + ks * KC;
        #pragma unroll 1
        for (int t = 0; t < KC; t += D) {
            float4 wv[D];
            #pragma unroll
            for (int u = 0; u < D; u++)
                wv[u] = __ldg((const float4*)(wp + (long)u * N));
            #pragma unroll
            for (int u = 0; u < D; u++) {
                u64 xv = xk[u];
                ffma2(a[0], xv, pack2(wv[u].x));
                ffma2(a[1], xv, pack2(wv[u].y));
                ffma2(a[2], xv, pack2(wv[u].z));
                ffma2(a[3], xv, pack2(wv[u].w));
            }
            wp += (long)D * N; xk += D;
        }
        if (ks > 0) {
            u64* ps = part + (((ks - 1) * NJW + jt) * 32 + lane) * 4;
            #pragma unroll
            for (int q = 0; q < 4; q++) ps[q] = a[q];
        }
    }
    __syncthreads();
    if (act && ks == 0) {
        #pragma unroll
        for (int h = 0; h < NK - 1; h++) {
            const u64* ps = part + ((h * NJW + jt) * 32 + lane) * 4;
            #pragma unroll
            for (int q = 0; q < 4; q++) a[q] = addf2(a[q], ps[q]);
        }
    }
    return act && (ks == 0);
}

// exp epilogue (linearized softmax): xh[j] = exp(v+b) packed; sinv[2] = 1/rowsum.
template <int NJW>
__device__ __forceinline__ void epi_exp(bool own, u64 (&a)[4], int j,
                                        const float* __restrict__ bias,
                                        u64* xh, float* red, float* sinv) {
    const int w = threadIdx.x >> 5, lane = threadIdx.x & 31;
    if (own) {
        float4 bv = __ldg((const float4*)(bias + j));
        float bq[4] = {bv.x, bv.y, bv.z, bv.w};
        float sl = 0.f, sh2 = 0.f;
        #pragma unroll
        for (int q = 0; q < 4; q++) {
            float lo = __expf(lohi(a[q], 0) + bq[q]);
            float hi = __expf(lohi(a[q], 1) + bq[q]);
            xh[j + q] = packf2(lo, hi);
            sl += lo; sh2 += hi;
        }
        #pragma unroll
        for (int o = 16; o; o >>= 1) {
            sl += __shfl_xor_sync(0xffffffffu, sl, o);
            sh2 += __shfl_xor_sync(0xffffffffu, sh2, o);
        }
        if (lane == 0) { red[w * 2] = sl; red[w * 2 + 1] = sh2; }
    }
    __syncthreads();
    if (threadIdx.x < 2) {
        float s = 0.f;
        #pragma unroll
        for (int h = 0; h < NJW; h++) s += red[h * 2 + (int)threadIdx.x];
        sinv[threadIdx.x] = 1.f / s;
    }
    __syncthreads();
}

// ================= K0: full fa_r / fa_u per 2-row block + updw + pack init =========
__global__ void __launch_bounds__(1024, 1) k0(
    const float* __restrict__ inputs,
    const float* __restrict__ r_w1, const float* __restrict__ r_b1,
    const float* __restrict__ r_w2, const float* __restrict__ r_b2,
    const float* __restrict__ u_w1, const float* __restrict__ u_b1,
    const float* __restrict__ u_w2, const float* __restrict__ u_b2,
    const float* __restrict__ W_uw, const float* __restrict__ b_uw) {
    extern __shared__ u64 sh[];
    const int tid = threadIdx.x, bx = blockIdx.x;
    if (bx == 16) {
        if (tid < 48) g_s.pack[tid] = 0ull;
        return;
    }
    u64* xs_in = sh;                 // 512
    u64* xsh = sh + 512;             // 512
    u64* part = sh + 1024;           // 3840 (max over stages)
    float* red = (float*)(sh + 4864);   // up to 8 floats
    float* sinv = (float*)(sh + 4868);  // 2 floats

    const int fu = bx >> 3;          // 0 = fa_r, 1 = fa_u
    const int r0 = (bx & 7) * 2;     // rows r0, r0+1

    if (tid < 512)
        xs_in[tid] = packf2(__ldg(inputs + r0 * 512 + tid),
                            __ldg(inputs + (r0 + 1) * 512 + tid));
    u64 a[4]; int j;
    bool own = bgemm<4, 8, 512, 512, 8>(xs_in, fu ? u_w1 : r_w1, a, part, j);
    epi_exp<4>(own, a, j, fu ? u_b1 : r_b1, xsh, red, sinv);
    own = bgemm<4, 8, 512, 512, 8>(xsh, fu ? u_w2 : r_w2, a, part, j);
    if (own) {
        float4 bv = __ldg((const float4*)((fu ? u_b2 : r_b2) + j));
        float bq[4] = {bv.x, bv.y, bv.z, bv.w};
        #pragma unroll
        for (int q = 0; q < 4; q++) {
            float vlo = lohi(a[q], 0) * sinv[0] + bq[q];
            float vhi = lohi(a[q], 1) * sinv[1] + bq[q];
            u64 xv = xs_in[j + q];
            float ylo = lohi(xv, 0) * vlo, yhi = lohi(xv, 1) * vhi;
            if (fu == 0) {
                g_s.yr[r0 * 512 + j + q] = ylo;
                g_s.yr[(r0 + 1) * 512 + j + q] = yhi;
            } else {
                xsh[j + q] = packf2(ylo, yhi);
            }
        }
    }
    if (fu == 1) {
        __syncthreads();
        const int w = tid >> 5, lane = tid & 31;
        if (w < 3) {
            u64 acc = 0ull;
            for (int k = lane; k < 512; k += 32)
                ffma2(acc, xsh[k], pack2(__ldg(W_uw + k * 3 + w)));
            #pragma unroll
            for (int o = 16; o; o >>= 1)
                acc = addf2(acc, __shfl_xor_sync(0xffffffffu, acc, o));
            if (lane == 0) {
                float bb = __ldg(b_uw + w);
                g_s.updw[r0 * 3 + w] = 1.f / (1.f + __expf(-(lohi(acc, 0) + bb)));
                g_s.updw[(r0 + 1) * 3 + w] = 1.f / (1.f + __expf(-(lohi(acc, 1) + bb)));
            }
        }
    }
}

// ================= K1: big read GEMM + fused max/argmax =================
__global__ void __launch_bounds__(512, 1) k1(const float* __restrict__ W,
                                             const float* __restrict__ bias) {
    extern __shared__ u64 shr[];
    u64* xs2 = shr;              // [k][pair] 512*8
    u64* part = shr + 4096;      // 4 slots * 3 * 32 * 16
    const int tid = threadIdx.x, bx = blockIdx.x;
    const int NB = gridDim.x;

    for (int idx = tid; idx < 4096; idx += 512) {
        int p = idx / 512, k = idx - p * 512;
        float lo = __ldcg(g_s.yr + (2 * p) * 512 + k);
        float hi = __ldcg(g_s.yr + (2 * p + 1) * 512 + k);
        xs2[k * 8 + p] = packf2(lo, hi);
    }
    __syncthreads();

    const int w = tid >> 5, lane = tid & 31;
    const int ts = w >> 2, kh = w & 3;
    const int base = 471 / NB, rem = 471 - base * NB;
    const int cnt = base + (bx < rem ? 1 : 0);
    const int start = bx * base + (bx < rem ? bx : rem);
    const bool act = ts < cnt;

    int isec = 0, j0 = 0, j1 = 0;
    long n0 = 0;
    bool v0 = false;
    u64 a0[8], a1[8];

    if (act) {
        int gtile = start + ts;
        isec = gtile / 157;
        int t = gtile - isec * 157;
        j0 = t * 64 + lane * 2; j1 = j0 + 1;
        v0 = j0 < 10000;
        n0 = (long)isec * 10000 + j0;
        #pragma unroll
        for (int p = 0; p < 8; p++) { a0[p] = 0ull; a1[p] = 0ull; }

        const float* W0 = W + (long)(kh * 128) * 30000;
        const u64* xk = xs2 + (kh * 128) * 8;
        #pragma unroll 1
        for (int it = 0; it < 128; it += 8) {
            float2 wv[8];
            #pragma unroll
            for (int u = 0; u < 8; u++)
                wv[u] = v0 ? __ldg((const float2*)(W0 + (long)u * 30000 + n0))
                           : make_float2(0.f, 0.f);
            #pragma unroll
            for (int u = 0; u < 8; u++) {
                u64 wa2 = pack2(wv[u].x), wb2 = pack2(wv[u].y);
                const u64* xp = xk + u * 8;
                #pragma unroll
                for (int p = 0; p < 8; p++) {
                    u64 xv = xp[p];
                    ffma2(a0[p], xv, wa2);
                    ffma2(a1[p], xv, wb2);
                }
            }
            W0 += 8L * 30000; xk += 64;
        }
        if (kh > 0) {
            u64* ps = part + ((ts * 3 + (kh - 1)) * 32 + lane) * 16;
            #pragma unroll
            for (int p = 0; p < 8; p++) { ps[p] = a0[p]; ps[8 + p] = a1[p]; }
        }
    }
    __syncthreads();

    if (act && kh == 0) {
        #pragma unroll
        for (int h = 0; h < 3; h++) {
            const u64* ps = part + ((ts * 3 + h) * 32 + lane) * 16;
            #pragma unroll
            for (int p = 0; p < 8; p++) {
                a0[p] = addf2(a0[p], ps[p]);
                a1[p] = addf2(a1[p], ps[8 + p]);
            }
        }
        float2 bv = v0 ? __ldg((const float2*)(bias + n0)) : make_float2(0.f, 0.f);
        #pragma unroll
        for (int b = 0; b < 16; b++) {
            float z0 = lohi(a0[b >> 1], b & 1) + bv.x;
            float z1 = lohi(a1[b >> 1], b & 1) + bv.y;
            u64 c0 = v0 ? (((u64)forder(z0) << 32) | (u64)(0xFFFFFFFFu - (unsigned)j0)) : 0ull;
            u64 c1 = v0 ? (((u64)forder(z1) << 32) | (u64)(0xFFFFFFFFu - (unsigned)j1)) : 0ull;
            u64 c = c0 > c1 ? c0 : c1;
            #pragma unroll
            for (int o = 16; o; o >>= 1) {
                u64 q = __shfl_xor_sync(0xffffffffu, c, o);
                if (q > c) c = q;
            }
            if (lane == 0) atomicMax(&g_s.pack[b * 3 + isec], c);
        }
    }
}

// ================= K2: fa_um (both stages) + r-update, per (i, 2 rows) ============
__global__ void __launch_bounds__(1024, 1) k2(
    const float* __restrict__ inputs, const float* __restrict__ memory,
    const float* __restrict__ um_w1, const float* __restrict__ um_b1,
    const float* __restrict__ um_w2, const float* __restrict__ um_b2,
    const float* __restrict__ W_um, const float* __restrict__ b_um) {
    extern __shared__ u64 sh[];
    u64* xs_cat = sh;                // 768
    u64* xsh = sh + 768;             // 768
    u64* part = sh + 1536;           // 3840 (max over stages)
    float* red = (float*)(sh + 5376);   // up to 12 floats (6 u64)
    float* sinv = (float*)(sh + 5382);  // 2 floats
    __shared__ long rowoff[2];
    __shared__ float su[2];

    const int tid = threadIdx.x, bx = blockIdx.x;
    const int i = bx >> 3;           // read slot
    const int r0 = (bx & 7) * 2;     // rows r0, r0+1

    if (tid < 2) {
        u64 p = __ldcg(&g_s.pack[(r0 + tid) * 3 + i]);
        unsigned idx = 0xFFFFFFFFu - (unsigned)(p & 0xFFFFFFFFull);
        rowoff[tid] = ((long)(r0 + tid) * 10000 + idx) * 256;
        su[tid] = __ldcg(&g_s.updw[(r0 + tid) * 3 + i]);
    }
    __syncthreads();
    if (tid < 768) {
        float lo, hi;
        if (tid < 256) {
            lo = __ldg(memory + rowoff[0] + tid);
            hi = __ldg(memory + rowoff[1] + tid);
        } else {
            lo = __ldg(inputs + r0 * 512 + (tid - 256));
            hi = __ldg(inputs + (r0 + 1) * 512 + (tid - 256));
        }
        xs_cat[tid] = packf2(lo, hi);
    }
    u64 a[4]; int j;
    bool own = bgemm<6, 4, 768, 768, 8>(xs_cat, um_w1, a, part, j);
    epi_exp<6>(own, a, j, um_b1, xsh, red, sinv);
    own = bgemm<6, 4, 768, 768, 8>(xsh, um_w2, a, part, j);
    if (own) {
        float4 bv = __ldg((const float4*)(um_b2 + j));
        float bq[4] = {bv.x, bv.y, bv.z, bv.w};
        #pragma unroll
        for (int q = 0; q < 4; q++) {
            float vlo = lohi(a[q], 0) * sinv[0] + bq[q];
            float vhi = lohi(a[q], 1) * sinv[1] + bq[q];
            u64 cv = xs_cat[j + q];
            xsh[j + q] = packf2(lohi(cv, 0) * vlo, lohi(cv, 1) * vhi);
        }
    }
    // r update: rc = u*relu(yum@W_um + b) + (1-u)*r
    own = bgemm<2, 16, 768, 256, 8>(xsh, W_um, a, part, j);
    if (own) {
        float4 bv = __ldg((const float4*)(b_um + j));
        float bq[4] = {bv.x, bv.y, bv.z, bv.w};
        float ulo = su[0], uhi = su[1];
        #pragma unroll
        for (int q = 0; q < 4; q++) {
            float vlo = fmaxf(lohi(a[q], 0) + bq[q], 0.f);
            float vhi = fmaxf(lohi(a[q], 1) + bq[q], 0.f);
            u64 rv = xs_cat[j + q];
            g_s.rc[i][r0 * 256 + j + q] = ulo * vlo + (1.f - ulo) * lohi(rv, 0);
            g_s.rc[i][(r0 + 1) * 256 + j + q] = uhi * vhi + (1.f - uhi) * lohi(rv, 1);
        }
    }
}

// ================= K3: full recurrent loop, 2 rows per block =================
__global__ void __launch_bounds__(1024, 1) k3(
    const float* __restrict__ am_w1, const float* __restrict__ am_b1,
    const float* __restrict__ am_w2, const float* __restrict__ am_b2,
    const float* __restrict__ W_am, const float* __restrict__ b_am,
    float* __restrict__ out) {
    extern __shared__ u64 sh[];
    u64* xs_c2 = sh;                 // 512: [rc(256) | m(256)]
    u64* xsh = sh + 512;             // 512
    u64* part = sh + 1024;           // 3840
    float* red = (float*)(sh + 4864);
    float* sinv = (float*)(sh + 4868);
    __shared__ float srw[6];         // [rr*3+i]

    const int tid = threadIdx.x;
    const int r0 = blockIdx.x * 2;

    if (tid < 6) {
        int rr = tid / 3, ii = tid - rr * 3;
        u64 p = __ldcg(&g_s.pack[(r0 + rr) * 3 + ii]);
        srw[tid] = tanhf(forder_inv((unsigned)(p >> 32)));
    }
    if (tid >= 256 && tid < 512) xs_c2[tid] = 0ull;

    u64 a[4]; int j;
    for (int i = 0; i < 3; i++) {
        if (tid < 256)
            xs_c2[tid] = packf2(__ldcg(g_s.rc[i] + r0 * 256 + tid),
                                __ldcg(g_s.rc[i] + (r0 + 1) * 256 + tid));
        bool own = bgemm<4, 8, 512, 512, 8>(xs_c2, am_w1, a, part, j);
        epi_exp<4>(own, a, j, am_b1, xsh, red, sinv);
        own = bgemm<4, 8, 512, 512, 8>(xsh, am_w2, a, part, j);
        if (own) {
            float4 bv = __ldg((const float4*)(am_b2 + j));
            float bq[4] = {bv.x, bv.y, bv.z, bv.w};
            #pragma unroll
            for (int q = 0; q < 4; q++) {
                float vlo = lohi(a[q], 0) * sinv[0] + bq[q];
                float vhi = lohi(a[q], 1) * sinv[1] + bq[q];
                u64 cv = xs_c2[j + q];
                xsh[j + q] = packf2(lohi(cv, 0) * vlo, lohi(cv, 1) * vhi);
            }
        }
        own = bgemm<2, 16, 512, 256, 8>(xsh, W_am, a, part, j);
        if (own) {
            float4 bv = __ldg((const float4*)(b_am + j));
            float bq[4] = {bv.x, bv.y, bv.z, bv.w};
            float rwlo = srw[i], rwhi = srw[3 + i];
            #pragma unroll
            for (int q = 0; q < 4; q++) {
                float mlo = rwlo * fmaxf(lohi(a[q], 0) + bq[q], 0.f);
                float mhi = rwhi * fmaxf(lohi(a[q], 1) + bq[q], 0.f);
                xs_c2[256 + j + q] = packf2(mlo, mhi);
                if (i == 2) {
                    out[r0 * 256 + j + q] = tanhf(mlo);
                    out[(r0 + 1) * 256 + j + q] = tanhf(mhi);
                }
            }
        }
        __syncthreads();
    }
}

// ---------------- host launcher ----------------
extern "C" void kernel_launch(void* const* d_in, const int* in_sizes, int n_in,
                              void* d_out, int out_size) {
    const float* inputs = (const float*)d_in[0];
    const float* memory = (const float*)d_in[1];
    const float* r_w1 = (const float*)d_in[2];
    const float* r_b1 = (const float*)d_in[3];
    const float* r_w2 = (const float*)d_in[4];
    const float* r_b2 = (const float*)d_in[5];
    const float* W_read = (const float*)d_in[6];
    const float* b_read = (const float*)d_in[7];
    const float* u_w1 = (const float*)d_in[8];
    const float* u_b1 = (const float*)d_in[9];
    const float* u_w2 = (const float*)d_in[10];
    const float* u_b2 = (const float*)d_in[11];
    const float* W_uw = (const float*)d_in[12];
    const float* b_uw = (const float*)d_in[13];
    const float* um_w1 = (const float*)d_in[14];
    const float* um_b1 = (const float*)d_in[15];
    const float* um_w2 = (const float*)d_in[16];
    const float* um_b2 = (const float*)d_in[17];
    const float* W_um = (const float*)d_in[18];
    const float* b_um = (const float*)d_in[19];
    const float* am_w1 = (const float*)d_in[20];
    const float* am_b1 = (const float*)d_in[21];
    const float* am_w2 = (const float*)d_in[22];
    const float* am_b2 = (const float*)d_in[23];
    const float* W_am = (const float*)d_in[24];
    const float* b_am = (const float*)d_in[25];
    float* out = (float*)d_out;

    static int NB = 0;
    if (NB == 0) {
        cudaDeviceGetAttribute(&NB, cudaDevAttrMultiProcessorCount, 0);
        if (NB <= 0) NB = 148;
    }
    const int DSM03 = 38976;  // 4872 u64 (xs 512 + xsh 512 + part 3840 + red/sinv)
    const int DSM1 = 81920;
    const int DSM2 = 43072;   // 5384 u64 (768 + 768 + 3840 + red/sinv)
    static bool attr_set = false;
    if (!attr_set) {
        cudaFuncSetAttribute(k0, cudaFuncAttributeMaxDynamicSharedMemorySize, DSM03);
        cudaFuncSetAttribute(k1, cudaFuncAttributeMaxDynamicSharedMemorySize, DSM1);
        cudaFuncSetAttribute(k2, cudaFuncAttributeMaxDynamicSharedMemorySize, DSM2);
        cudaFuncSetAttribute(k3, cudaFuncAttributeMaxDynamicSharedMemorySize, DSM03);
        attr_set = true;
    }

    k0<<<17, 1024, DSM03>>>(inputs, r_w1, r_b1, r_w2, r_b2,
                            u_w1, u_b1, u_w2, u_b2, W_uw, b_uw);
    k1<<<NB, 512, DSM1>>>(W_read, b_read);
    k2<<<24, 1024, DSM2>>>(inputs, memory, um_w1, um_b1, um_w2, um_b2, W_um, b_um);
    k3<<<8, 1024, DSM03>>>(am_w1, am_b1, am_w2, am_b2, W_am, b_am, out);
}

// round 12
// speedup vs baseline: 2.4522x; 1.1093x over previous
#include <cuda_runtime.h>
#include <cstdint>

typedef unsigned long long u64;

// ---------------- scratch (no allocations allowed) ----------------
struct Scratch {
    float yr[16 * 512];          // fa_r output rows
    float rc[3][16 * 256];       // precomputed updated r per read-slot
    float updw[48];              // sigmoid update weights [b*3+i]
    u64 pack[48];                // (orderable_max << 32 | ~idx)
};
__device__ Scratch g_s;

__device__ __forceinline__ unsigned forder(float f) {
    unsigned u = __float_as_uint(f);
    return (u & 0x80000000u) ? ~u : (u | 0x80000000u);
}
__device__ __forceinline__ float forder_inv(unsigned u) {
    unsigned v = (u & 0x80000000u) ? (u & 0x7FFFFFFFu) : ~u;
    return __uint_as_float(v);
}
__device__ __forceinline__ u64 pack2(float f) {
    unsigned u = __float_as_uint(f);
    return ((u64)u << 32) | (u64)u;
}
__device__ __forceinline__ u64 packf2(float lo, float hi) {
    return ((u64)__float_as_uint(hi) << 32) | (u64)__float_as_uint(lo);
}
__device__ __forceinline__ void ffma2(u64& acc, u64 x, u64 w) {
    asm("fma.rn.f32x2 %0, %1, %2, %0;" : "+l"(acc) : "l"(x), "l"(w));
}
__device__ __forceinline__ u64 addf2(u64 a, u64 b) {
    u64 d;
    asm("add.rn.f32x2 %0, %1, %2;" : "=l"(d) : "l"(a), "l"(b));
    return d;
}
__device__ __forceinline__ float lohi(u64 v, int hi) {
    return __uint_as_float(hi ? (unsigned)(v >> 32) : (unsigned)v);
}
__device__ __forceinline__ uint32_t smem_u32(const void* p) {
    return (uint32_t)__cvta_generic_to_shared(p);
}
__device__ __forceinline__ void dsmem_st64(uint32_t laddr, uint32_t peer, u64 v) {
    uint32_t r;
    asm volatile("mapa.shared::cluster.u32 %0, %1, %2;" : "=r"(r) : "r"(laddr), "r"(peer));
    asm volatile("st.shared::cluster.b64 [%0], %1;" :: "r"(r), "l"(v) : "memory");
}
__device__ __forceinline__ void dsmem_stf(uint32_t laddr, uint32_t peer, float v) {
    uint32_t r;
    asm volatile("mapa.shared::cluster.u32 %0, %1, %2;" : "=r"(r) : "r"(laddr), "r"(peer));
    asm volatile("st.shared::cluster.f32 [%0], %1;" :: "r"(r), "f"(v) : "memory");
}
#define CLUSTER_SYNC() do { \
    asm volatile("barrier.cluster.arrive.aligned;" ::: "memory"); \
    asm volatile("barrier.cluster.wait.aligned;" ::: "memory"); } while (0)

// ---------- block GEMM (row-pair packed): warp (jt, ks); D = prefetch depth ----------
template <int NJW, int NK, int K, int N, int D>
__device__ __forceinline__ bool bgemm(const u64* __restrict__ xs2,
                                      const float* __restrict__ W,
                                      u64 (&a)[4], u64* part, int& jout) {
    const int tid = threadIdx.x, w = tid >> 5, lane = tid & 31;
    const int jt = w % NJW, ks = w / NJW;
    const bool act = w < NJW * NK;
    jout = jt * 128 + lane * 4;
    constexpr int KC = K / NK;
    __syncthreads();   // protects part + input buffers from previous stage
    #pragma unroll
    for (int q = 0; q < 4; q++) a[q] = 0ull;
    if (act) {
        const float* wp = W + (long)(ks * KC) * N + jout;
        const u64* xk = xs2 + ks * KC;
        #pragma unroll 1
        for (int t = 0; t < KC; t += D) {
            float4 wv[D];
            #pragma unroll
            for (int u = 0; u < D; u++)
                wv[u] = __ldg((const float4*)(wp + (long)u * N));
            #pragma unroll
            for (int u = 0; u < D; u++) {
                u64 xv = xk[u];
                ffma2(a[0], xv, pack2(wv[u].x));
                ffma2(a[1], xv, pack2(wv[u].y));
                ffma2(a[2], xv, pack2(wv[u].z));
                ffma2(a[3], xv, pack2(wv[u].w));
            }
            wp += (long)D * N; xk += D;
        }
        if (ks > 0) {
            u64* ps = part + (((ks - 1) * NJW + jt) * 32 + lane) * 4;
            #pragma unroll
            for (int q = 0; q < 4; q++) ps[q] = a[q];
        }
    }
    __syncthreads();
    if (act && ks == 0) {
        #pragma unroll
        for (int h = 0; h < NK - 1; h++) {
            const u64* ps = part + ((h * NJW + jt) * 32 + lane) * 4;
            #pragma unroll
            for (int q = 0; q < 4; q++) a[q] = addf2(a[q], ps[q]);
        }
    }
    return act && (ks == 0);
}

// exp epilogue (linearized softmax): xh[j] = exp(v+b) packed; sinv[2] = 1/rowsum.
template <int NJW>
__device__ __forceinline__ void epi_exp(bool own, u64 (&a)[4], int j,
                                        const float* __restrict__ bias,
                                        u64* xh, float* red, float* sinv) {
    const int w = threadIdx.x >> 5, lane = threadIdx.x & 31;
    if (own) {
        float4 bv = __ldg((const float4*)(bias + j));
        float bq[4] = {bv.x, bv.y, bv.z, bv.w};
        float sl = 0.f, sh2 = 0.f;
        #pragma unroll
        for (int q = 0; q < 4; q++) {
            float lo = __expf(lohi(a[q], 0) + bq[q]);
            float hi = __expf(lohi(a[q], 1) + bq[q]);
            xh[j + q] = packf2(lo, hi);
            sl += lo; sh2 += hi;
        }
        #pragma unroll
        for (int o = 16; o; o >>= 1) {
            sl += __shfl_xor_sync(0xffffffffu, sl, o);
            sh2 += __shfl_xor_sync(0xffffffffu, sh2, o);
        }
        if (lane == 0) { red[w * 2] = sl; red[w * 2 + 1] = sh2; }
    }
    __syncthreads();
    if (threadIdx.x < 2) {
        float s = 0.f;
        #pragma unroll
        for (int h = 0; h < NJW; h++) s += red[h * 2 + (int)threadIdx.x];
        sinv[threadIdx.x] = 1.f / s;
    }
    __syncthreads();
}

// ================= K0: full fa_r / fa_u per 2-row block + updw + pack init =========
__global__ void __launch_bounds__(1024, 1) k0(
    const float* __restrict__ inputs,
    const float* __restrict__ r_w1, const float* __restrict__ r_b1,
    const float* __restrict__ r_w2, const float* __restrict__ r_b2,
    const float* __restrict__ u_w1, const float* __restrict__ u_b1,
    const float* __restrict__ u_w2, const float* __restrict__ u_b2,
    const float* __restrict__ W_uw, const float* __restrict__ b_uw) {
    extern __shared__ u64 sh[];
    const int tid = threadIdx.x, bx = blockIdx.x;
    if (bx == 16) {
        if (tid < 48) g_s.pack[tid] = 0ull;
        return;
    }
    u64* xs_in = sh;                 // 512
    u64* xsh = sh + 512;             // 512
    u64* part = sh + 1024;           // 3840
    float* red = (float*)(sh + 4864);
    float* sinv = (float*)(sh + 4868);

    const int fu = bx >> 3;
    const int r0 = (bx & 7) * 2;

    if (tid < 512)
        xs_in[tid] = packf2(__ldg(inputs + r0 * 512 + tid),
                            __ldg(inputs + (r0 + 1) * 512 + tid));
    u64 a[4]; int j;
    bool own = bgemm<4, 8, 512, 512, 8>(xs_in, fu ? u_w1 : r_w1, a, part, j);
    epi_exp<4>(own, a, j, fu ? u_b1 : r_b1, xsh, red, sinv);
    own = bgemm<4, 8, 512, 512, 8>(xsh, fu ? u_w2 : r_w2, a, part, j);
    if (own) {
        float4 bv = __ldg((const float4*)((fu ? u_b2 : r_b2) + j));
        float bq[4] = {bv.x, bv.y, bv.z, bv.w};
        #pragma unroll
        for (int q = 0; q < 4; q++) {
            float vlo = lohi(a[q], 0) * sinv[0] + bq[q];
            float vhi = lohi(a[q], 1) * sinv[1] + bq[q];
            u64 xv = xs_in[j + q];
            float ylo = lohi(xv, 0) * vlo, yhi = lohi(xv, 1) * vhi;
            if (fu == 0) {
                g_s.yr[r0 * 512 + j + q] = ylo;
                g_s.yr[(r0 + 1) * 512 + j + q] = yhi;
            } else {
                xsh[j + q] = packf2(ylo, yhi);
            }
        }
    }
    if (fu == 1) {
        __syncthreads();
        const int w = tid >> 5, lane = tid & 31;
        if (w < 3) {
            u64 acc = 0ull;
            for (int k = lane; k < 512; k += 32)
                ffma2(acc, xsh[k], pack2(__ldg(W_uw + k * 3 + w)));
            #pragma unroll
            for (int o = 16; o; o >>= 1)
                acc = addf2(acc, __shfl_xor_sync(0xffffffffu, acc, o));
            if (lane == 0) {
                float bb = __ldg(b_uw + w);
                g_s.updw[r0 * 3 + w] = 1.f / (1.f + __expf(-(lohi(acc, 0) + bb)));
                g_s.updw[(r0 + 1) * 3 + w] = 1.f / (1.f + __expf(-(lohi(acc, 1) + bb)));
            }
        }
    }
}

// ================= K1: big read GEMM + fused max/argmax =================
__global__ void __launch_bounds__(512, 1) k1(const float* __restrict__ W,
                                             const float* __restrict__ bias) {
    extern __shared__ u64 shr[];
    u64* xs2 = shr;              // [k][pair] 512*8
    u64* part = shr + 4096;      // 4 slots * 3 * 32 * 16
    const int tid = threadIdx.x, bx = blockIdx.x;
    const int NB = gridDim.x;

    for (int idx = tid; idx < 4096; idx += 512) {
        int p = idx / 512, k = idx - p * 512;
        float lo = __ldcg(g_s.yr + (2 * p) * 512 + k);
        float hi = __ldcg(g_s.yr + (2 * p + 1) * 512 + k);
        xs2[k * 8 + p] = packf2(lo, hi);
    }
    __syncthreads();

    const int w = tid >> 5, lane = tid & 31;
    const int ts = w >> 2, kh = w & 3;
    const int base = 471 / NB, rem = 471 - base * NB;
    const int cnt = base + (bx < rem ? 1 : 0);
    const int start = bx * base + (bx < rem ? bx : rem);
    const bool act = ts < cnt;

    int isec = 0, j0 = 0, j1 = 0;
    long n0 = 0;
    bool v0 = false;
    u64 a0[8], a1[8];

    if (act) {
        int gtile = start + ts;
        isec = gtile / 157;
        int t = gtile - isec * 157;
        j0 = t * 64 + lane * 2; j1 = j0 + 1;
        v0 = j0 < 10000;
        n0 = (long)isec * 10000 + j0;
        #pragma unroll
        for (int p = 0; p < 8; p++) { a0[p] = 0ull; a1[p] = 0ull; }

        const float* W0 = W + (long)(kh * 128) * 30000;
        const u64* xk = xs2 + (kh * 128) * 8;
        #pragma unroll 1
        for (int it = 0; it < 128; it += 8) {
            float2 wv[8];
            #pragma unroll
            for (int u = 0; u < 8; u++)
                wv[u] = v0 ? __ldg((const float2*)(W0 + (long)u * 30000 + n0))
                           : make_float2(0.f, 0.f);
            #pragma unroll
            for (int u = 0; u < 8; u++) {
                u64 wa2 = pack2(wv[u].x), wb2 = pack2(wv[u].y);
                const u64* xp = xk + u * 8;
                #pragma unroll
                for (int p = 0; p < 8; p++) {
                    u64 xv = xp[p];
                    ffma2(a0[p], xv, wa2);
                    ffma2(a1[p], xv, wb2);
                }
            }
            W0 += 8L * 30000; xk += 64;
        }
        if (kh > 0) {
            u64* ps = part + ((ts * 3 + (kh - 1)) * 32 + lane) * 16;
            #pragma unroll
            for (int p = 0; p < 8; p++) { ps[p] = a0[p]; ps[8 + p] = a1[p]; }
        }
    }
    __syncthreads();

    if (act && kh == 0) {
        #pragma unroll
        for (int h = 0; h < 3; h++) {
            const u64* ps = part + ((ts * 3 + h) * 32 + lane) * 16;
            #pragma unroll
            for (int p = 0; p < 8; p++) {
                a0[p] = addf2(a0[p], ps[p]);
                a1[p] = addf2(a1[p], ps[8 + p]);
            }
        }
        float2 bv = v0 ? __ldg((const float2*)(bias + n0)) : make_float2(0.f, 0.f);
        #pragma unroll
        for (int b = 0; b < 16; b++) {
            float z0 = lohi(a0[b >> 1], b & 1) + bv.x;
            float z1 = lohi(a1[b >> 1], b & 1) + bv.y;
            u64 c0 = v0 ? (((u64)forder(z0) << 32) | (u64)(0xFFFFFFFFu - (unsigned)j0)) : 0ull;
            u64 c1 = v0 ? (((u64)forder(z1) << 32) | (u64)(0xFFFFFFFFu - (unsigned)j1)) : 0ull;
            u64 c = c0 > c1 ? c0 : c1;
            #pragma unroll
            for (int o = 16; o; o >>= 1) {
                u64 q = __shfl_xor_sync(0xffffffffu, c, o);
                if (q > c) c = q;
            }
            if (lane == 0) atomicMax(&g_s.pack[b * 3 + isec], c);
        }
    }
}

// ================= K2: fa_um (both stages) + r-update, per (i, 2 rows) ============
__global__ void __launch_bounds__(1024, 1) k2(
    const float* __restrict__ inputs, const float* __restrict__ memory,
    const float* __restrict__ um_w1, const float* __restrict__ um_b1,
    const float* __restrict__ um_w2, const float* __restrict__ um_b2,
    const float* __restrict__ W_um, const float* __restrict__ b_um) {
    extern __shared__ u64 sh[];
    u64* xs_cat = sh;                // 768
    u64* xsh = sh + 768;             // 768
    u64* part = sh + 1536;           // 3840
    float* red = (float*)(sh + 5376);
    float* sinv = (float*)(sh + 5382);
    __shared__ long rowoff[2];
    __shared__ float su[2];

    const int tid = threadIdx.x, bx = blockIdx.x;
    const int i = bx >> 3;
    const int r0 = (bx & 7) * 2;

    if (tid < 2) {
        u64 p = __ldcg(&g_s.pack[(r0 + tid) * 3 + i]);
        unsigned idx = 0xFFFFFFFFu - (unsigned)(p & 0xFFFFFFFFull);
        rowoff[tid] = ((long)(r0 + tid) * 10000 + idx) * 256;
        su[tid] = __ldcg(&g_s.updw[(r0 + tid) * 3 + i]);
    }
    __syncthreads();
    if (tid < 768) {
        float lo, hi;
        if (tid < 256) {
            lo = __ldg(memory + rowoff[0] + tid);
            hi = __ldg(memory + rowoff[1] + tid);
        } else {
            lo = __ldg(inputs + r0 * 512 + (tid - 256));
            hi = __ldg(inputs + (r0 + 1) * 512 + (tid - 256));
        }
        xs_cat[tid] = packf2(lo, hi);
    }
    u64 a[4]; int j;
    bool own = bgemm<6, 4, 768, 768, 8>(xs_cat, um_w1, a, part, j);
    epi_exp<6>(own, a, j, um_b1, xsh, red, sinv);
    own = bgemm<6, 4, 768, 768, 8>(xsh, um_w2, a, part, j);
    if (own) {
        float4 bv = __ldg((const float4*)(um_b2 + j));
        float bq[4] = {bv.x, bv.y, bv.z, bv.w};
        #pragma unroll
        for (int q = 0; q < 4; q++) {
            float vlo = lohi(a[q], 0) * sinv[0] + bq[q];
            float vhi = lohi(a[q], 1) * sinv[1] + bq[q];
            u64 cv = xs_cat[j + q];
            xsh[j + q] = packf2(lohi(cv, 0) * vlo, lohi(cv, 1) * vhi);
        }
    }
    own = bgemm<2, 16, 768, 256, 8>(xsh, W_um, a, part, j);
    if (own) {
        float4 bv = __ldg((const float4*)(b_um + j));
        float bq[4] = {bv.x, bv.y, bv.z, bv.w};
        float ulo = su[0], uhi = su[1];
        #pragma unroll
        for (int q = 0; q < 4; q++) {
            float vlo = fmaxf(lohi(a[q], 0) + bq[q], 0.f);
            float vhi = fmaxf(lohi(a[q], 1) + bq[q], 0.f);
            u64 rv = xs_cat[j + q];
            g_s.rc[i][r0 * 256 + j + q] = ulo * vlo + (1.f - ulo) * lohi(rv, 0);
            g_s.rc[i][(r0 + 1) * 256 + j + q] = uhi * vhi + (1.f - uhi) * lohi(rv, 1);
        }
    }
}

// ================= K3: recurrent loop, 2 rows per 2-CTA cluster (j-split) =========
__global__ void __launch_bounds__(1024, 1) __cluster_dims__(2, 1, 1) k3(
    const float* __restrict__ am_w1, const float* __restrict__ am_b1,
    const float* __restrict__ am_w2, const float* __restrict__ am_b2,
    const float* __restrict__ W_am, const float* __restrict__ b_am,
    float* __restrict__ out) {
    extern __shared__ u64 sh[];
    u64* A = sh;                     // 512: [rc(256) | m(256)]
    u64* B = sh + 512;               // 512: exp values
    u64* C = sh + 1024;              // 512: yam values
    u64* part = sh + 1536;           // 3968 (GEMM3 NK=32)
    float* red = (float*)(sh + 5504);   // 4 floats
    float* psA = (float*)(sh + 5506);   // own partial sums [2]
    float* psB = (float*)(sh + 5507);   // peer partial sums [2]
    float* sinv = (float*)(sh + 5508);  // 2 floats
    __shared__ float srw[6];

    const int tid = threadIdx.x;
    uint32_t rank;
    asm("mov.u32 %0, %%cluster_ctarank;" : "=r"(rank));
    const uint32_t peer = rank ^ 1u;
    const int r0 = (blockIdx.x >> 1) * 2;

    if (tid < 6) {
        int rr = tid / 3, ii = tid - rr * 3;
        u64 p = __ldcg(&g_s.pack[(r0 + rr) * 3 + ii]);
        srw[tid] = tanhf(forder_inv((unsigned)(p >> 32)));
    }
    if (tid >= 256 && tid < 512) A[tid] = 0ull;   // m = 0

    u64 a[4]; int j;
    for (int i = 0; i < 3; i++) {
        if (tid < 256)
            A[tid] = packf2(__ldcg(g_s.rc[i] + r0 * 256 + tid),
                            __ldcg(g_s.rc[i] + (r0 + 1) * 256 + tid));
        // ---- GEMM1: h = A @ am_w1[:, rank*256 + jl], exp -> B (own + peer) ----
        bool own = bgemm<2, 16, 512, 512, 8>(A, am_w1 + rank * 256, a, part, j);
        {
            const int w = tid >> 5, lane = tid & 31;
            if (own) {
                int gj = rank * 256 + j;
                float4 bv = __ldg((const float4*)(am_b1 + gj));
                float bq[4] = {bv.x, bv.y, bv.z, bv.w};
                float sl = 0.f, sh2 = 0.f;
                #pragma unroll
                for (int q = 0; q < 4; q++) {
                    float lo = __expf(lohi(a[q], 0) + bq[q]);
                    float hi = __expf(lohi(a[q], 1) + bq[q]);
                    u64 v = packf2(lo, hi);
                    B[gj + q] = v;
                    dsmem_st64(smem_u32(&B[gj + q]), peer, v);
                    sl += lo; sh2 += hi;
                }
                #pragma unroll
                for (int o = 16; o; o >>= 1) {
                    sl += __shfl_xor_sync(0xffffffffu, sl, o);
                    sh2 += __shfl_xor_sync(0xffffffffu, sh2, o);
                }
                if (lane == 0) { red[w * 2] = sl; red[w * 2 + 1] = sh2; }
            }
            __syncthreads();
            if (tid < 2) {
                float s = red[tid] + red[2 + tid];
                psA[tid] = s;
                dsmem_stf(smem_u32(&psB[tid]), peer, s);
            }
        }
        CLUSTER_SYNC();
        if (tid < 2) sinv[tid] = 1.f / (psA[tid] + psB[tid]);
        // ---- GEMM2: y = A * (softmax @ am_w2 + b) -> C (own + peer) ----
        own = bgemm<2, 16, 512, 512, 8>(B, am_w2 + rank * 256, a, part, j);
        if (own) {
            int gj = rank * 256 + j;
            float4 bv = __ldg((const float4*)(am_b2 + gj));
            float bq[4] = {bv.x, bv.y, bv.z, bv.w};
            #pragma unroll
            for (int q = 0; q < 4; q++) {
                float vlo = lohi(a[q], 0) * sinv[0] + bq[q];
                float vhi = lohi(a[q], 1) * sinv[1] + bq[q];
                u64 cv = A[gj + q];
                u64 y = packf2(lohi(cv, 0) * vlo, lohi(cv, 1) * vhi);
                C[gj + q] = y;
                dsmem_st64(smem_u32(&C[gj + q]), peer, y);
            }
        }
        CLUSTER_SYNC();
        // ---- GEMM3: m = rw * relu(C @ W_am[:, rank*128 + jl] + b) -> A[256+] ----
        own = bgemm<1, 32, 512, 256, 8>(C, W_am + rank * 128, a, part, j);
        if (own) {
            int gj = rank * 128 + j;
            float4 bv = __ldg((const float4*)(b_am + gj));
            float bq[4] = {bv.x, bv.y, bv.z, bv.w};
            float rwlo = srw[i], rwhi = srw[3 + i];
            #pragma unroll
            for (int q = 0; q < 4; q++) {
                float mlo = rwlo * fmaxf(lohi(a[q], 0) + bq[q], 0.f);
                float mhi = rwhi * fmaxf(lohi(a[q], 1) + bq[q], 0.f);
                u64 mv = packf2(mlo, mhi);
                A[256 + gj + q] = mv;
                dsmem_st64(smem_u32(&A[256 + gj + q]), peer, mv);
                if (i == 2) {
                    out[r0 * 256 + gj + q] = tanhf(mlo);
                    out[(r0 + 1) * 256 + gj + q] = tanhf(mhi);
                }
            }
        }
        CLUSTER_SYNC();
    }
}

// ---------------- host launcher ----------------
extern "C" void kernel_launch(void* const* d_in, const int* in_sizes, int n_in,
                              void* d_out, int out_size) {
    const float* inputs = (const float*)d_in[0];
    const float* memory = (const float*)d_in[1];
    const float* r_w1 = (const float*)d_in[2];
    const float* r_b1 = (const float*)d_in[3];
    const float* r_w2 = (const float*)d_in[4];
    const float* r_b2 = (const float*)d_in[5];
    const float* W_read = (const float*)d_in[6];
    const float* b_read = (const float*)d_in[7];
    const float* u_w1 = (const float*)d_in[8];
    const float* u_b1 = (const float*)d_in[9];
    const float* u_w2 = (const float*)d_in[10];
    const float* u_b2 = (const float*)d_in[11];
    const float* W_uw = (const float*)d_in[12];
    const float* b_uw = (const float*)d_in[13];
    const float* um_w1 = (const float*)d_in[14];
    const float* um_b1 = (const float*)d_in[15];
    const float* um_w2 = (const float*)d_in[16];
    const float* um_b2 = (const float*)d_in[17];
    const float* W_um = (const float*)d_in[18];
    const float* b_um = (const float*)d_in[19];
    const float* am_w1 = (const float*)d_in[20];
    const float* am_b1 = (const float*)d_in[21];
    const float* am_w2 = (const float*)d_in[22];
    const float* am_b2 = (const float*)d_in[23];
    const float* W_am = (const float*)d_in[24];
    const float* b_am = (const float*)d_in[25];
    float* out = (float*)d_out;

    static int NB = 0;
    if (NB == 0) {
        cudaDeviceGetAttribute(&NB, cudaDevAttrMultiProcessorCount, 0);
        if (NB <= 0) NB = 148;
    }
    const int DSM0 = 38976;   // k0: 4872 u64
    const int DSM1 = 81920;   // k1
    const int DSM2 = 43072;   // k2: 5384 u64
    const int DSM3 = 44080;   // k3: 5510 u64
    static bool attr_set = false;
    if (!attr_set) {
        cudaFuncSetAttribute(k0, cudaFuncAttributeMaxDynamicSharedMemorySize, DSM0);
        cudaFuncSetAttribute(k1, cudaFuncAttributeMaxDynamicSharedMemorySize, DSM1);
        cudaFuncSetAttribute(k2, cudaFuncAttributeMaxDynamicSharedMemorySize, DSM2);
        cudaFuncSetAttribute(k3, cudaFuncAttributeMaxDynamicSharedMemorySize, DSM3);
        attr_set = true;
    }

    k0<<<17, 1024, DSM0>>>(inputs, r_w1, r_b1, r_w2, r_b2,
                           u_w1, u_b1, u_w2, u_b2, W_uw, b_uw);
    k1<<<NB, 512, DSM1>>>(W_read, b_read);
    k2<<<24, 1024, DSM2>>>(inputs, memory, um_w1, um_b1, um_w2, um_b2, W_um, b_um);
    k3<<<16, 1024, DSM3>>>(am_w1, am_b1, am_w2, am_b2, W_am, b_am, out);
}

// round 13
// speedup vs baseline: 2.8533x; 1.1636x over previous
#include <cuda_runtime.h>
#include <cstdint>

typedef unsigned long long u64;

// ---------------- scratch (no allocations allowed) ----------------
struct Scratch {
    float yr[16 * 512];          // fa_r output rows
    float rc[3][16 * 256];       // precomputed updated r per read-slot
    float updw[48];              // sigmoid update weights [b*3+i]
    u64 pack[48];                // (orderable_max << 32 | ~idx)
};
__device__ Scratch g_s;

__device__ __forceinline__ unsigned forder(float f) {
    unsigned u = __float_as_uint(f);
    return (u & 0x80000000u) ? ~u : (u | 0x80000000u);
}
__device__ __forceinline__ float forder_inv(unsigned u) {
    unsigned v = (u & 0x80000000u) ? (u & 0x7FFFFFFFu) : ~u;
    return __uint_as_float(v);
}
__device__ __forceinline__ u64 pack2(float f) {
    unsigned u = __float_as_uint(f);
    return ((u64)u << 32) | (u64)u;
}
__device__ __forceinline__ u64 packf2(float lo, float hi) {
    return ((u64)__float_as_uint(hi) << 32) | (u64)__float_as_uint(lo);
}
__device__ __forceinline__ void ffma2(u64& acc, u64 x, u64 w) {
    asm("fma.rn.f32x2 %0, %1, %2, %0;" : "+l"(acc) : "l"(x), "l"(w));
}
__device__ __forceinline__ u64 addf2(u64 a, u64 b) {
    u64 d;
    asm("add.rn.f32x2 %0, %1, %2;" : "=l"(d) : "l"(a), "l"(b));
    return d;
}
__device__ __forceinline__ float lohi(u64 v, int hi) {
    return __uint_as_float(hi ? (unsigned)(v >> 32) : (unsigned)v);
}
__device__ __forceinline__ uint32_t smem_u32(const void* p) {
    return (uint32_t)__cvta_generic_to_shared(p);
}
__device__ __forceinline__ void dsmem_st64(uint32_t laddr, uint32_t peer, u64 v) {
    uint32_t r;
    asm volatile("mapa.shared::cluster.u32 %0, %1, %2;" : "=r"(r) : "r"(laddr), "r"(peer));
    asm volatile("st.shared::cluster.b64 [%0], %1;" :: "r"(r), "l"(v) : "memory");
}
__device__ __forceinline__ void dsmem_stf(uint32_t laddr, uint32_t peer, float v) {
    uint32_t r;
    asm volatile("mapa.shared::cluster.u32 %0, %1, %2;" : "=r"(r) : "r"(laddr), "r"(peer));
    asm volatile("st.shared::cluster.f32 [%0], %1;" :: "r"(r), "f"(v) : "memory");
}
#define CLUSTER_SYNC() do { \
    asm volatile("barrier.cluster.arrive.aligned;" ::: "memory"); \
    asm volatile("barrier.cluster.wait.aligned;" ::: "memory"); } while (0)

// ---------- block GEMM (row-pair packed): warp (jt, ks); 128 cols per j-warp ----------
template <int NJW, int NK, int K, int N, int D>
__device__ __forceinline__ bool bgemm(const u64* __restrict__ xs2,
                                      const float* __restrict__ W,
                                      u64 (&a)[4], u64* part, int& jout) {
    const int tid = threadIdx.x, w = tid >> 5, lane = tid & 31;
    const int jt = w % NJW, ks = w / NJW;
    const bool act = w < NJW * NK;
    jout = jt * 128 + lane * 4;
    constexpr int KC = K / NK;
    __syncthreads();   // protects part + input buffers from previous stage
    #pragma unroll
    for (int q = 0; q < 4; q++) a[q] = 0ull;
    if (act) {
        const float* wp = W + (long)(ks * KC) * N + jout;
        const u64* xk = xs2 + ks * KC;
        #pragma unroll 1
        for (int t = 0; t < KC; t += D) {
            float4 wv[D];
            #pragma unroll
            for (int u = 0; u < D; u++)
                wv[u] = __ldg((const float4*)(wp + (long)u * N));
            #pragma unroll
            for (int u = 0; u < D; u++) {
                u64 xv = xk[u];
                ffma2(a[0], xv, pack2(wv[u].x));
                ffma2(a[1], xv, pack2(wv[u].y));
                ffma2(a[2], xv, pack2(wv[u].z));
                ffma2(a[3], xv, pack2(wv[u].w));
            }
            wp += (long)D * N; xk += D;
        }
        if (ks > 0) {
            u64* ps = part + (((ks - 1) * NJW + jt) * 32 + lane) * 4;
            #pragma unroll
            for (int q = 0; q < 4; q++) ps[q] = a[q];
        }
    }
    __syncthreads();
    if (act && ks == 0) {
        #pragma unroll
        for (int h = 0; h < NK - 1; h++) {
            const u64* ps = part + ((h * NJW + jt) * 32 + lane) * 4;
            #pragma unroll
            for (int q = 0; q < 4; q++) a[q] = addf2(a[q], ps[q]);
        }
    }
    return act && (ks == 0);
}

// ---------- narrow block GEMM: single j-warp covering 64 cols (float2 loads) ----------
template <int NK, int K, int N, int D>
__device__ __forceinline__ bool bgemm2(const u64* __restrict__ xs2,
                                       const float* __restrict__ W,
                                       u64 (&a)[2], u64* part, int& jout) {
    const int tid = threadIdx.x, w = tid >> 5, lane = tid & 31;
    const int ks = w;
    const bool act = w < NK;
    jout = lane * 2;
    constexpr int KC = K / NK;
    __syncthreads();
    a[0] = 0ull; a[1] = 0ull;
    if (act) {
        const float* wp = W + (long)(ks * KC) * N + jout;
        const u64* xk = xs2 + ks * KC;
        #pragma unroll 1
        for (int t = 0; t < KC; t += D) {
            float2 wv[D];
            #pragma unroll
            for (int u = 0; u < D; u++)
                wv[u] = __ldg((const float2*)(wp + (long)u * N));
            #pragma unroll
            for (int u = 0; u < D; u++) {
                u64 xv = xk[u];
                ffma2(a[0], xv, pack2(wv[u].x));
                ffma2(a[1], xv, pack2(wv[u].y));
            }
            wp += (long)D * N; xk += D;
        }
        if (ks > 0) {
            u64* ps = part + ((ks - 1) * 32 + lane) * 2;
            ps[0] = a[0]; ps[1] = a[1];
        }
    }
    __syncthreads();
    if (act && ks == 0) {
        #pragma unroll
        for (int h = 0; h < NK - 1; h++) {
            const u64* ps = part + (h * 32 + lane) * 2;
            a[0] = addf2(a[0], ps[0]);
            a[1] = addf2(a[1], ps[1]);
        }
    }
    return act && (ks == 0);
}

// exp epilogue for non-clustered kernels
template <int NJW>
__device__ __forceinline__ void epi_exp(bool own, u64 (&a)[4], int j,
                                        const float* __restrict__ bias,
                                        u64* xh, float* red, float* sinv) {
    const int w = threadIdx.x >> 5, lane = threadIdx.x & 31;
    if (own) {
        float4 bv = __ldg((const float4*)(bias + j));
        float bq[4] = {bv.x, bv.y, bv.z, bv.w};
        float sl = 0.f, sh2 = 0.f;
        #pragma unroll
        for (int q = 0; q < 4; q++) {
            float lo = __expf(lohi(a[q], 0) + bq[q]);
            float hi = __expf(lohi(a[q], 1) + bq[q]);
            xh[j + q] = packf2(lo, hi);
            sl += lo; sh2 += hi;
        }
        #pragma unroll
        for (int o = 16; o; o >>= 1) {
            sl += __shfl_xor_sync(0xffffffffu, sl, o);
            sh2 += __shfl_xor_sync(0xffffffffu, sh2, o);
        }
        if (lane == 0) { red[w * 2] = sl; red[w * 2 + 1] = sh2; }
    }
    __syncthreads();
    if (threadIdx.x < 2) {
        float s = 0.f;
        #pragma unroll
        for (int h = 0; h < NJW; h++) s += red[h * 2 + (int)threadIdx.x];
        sinv[threadIdx.x] = 1.f / s;
    }
    __syncthreads();
}

// ================= K0: full fa_r / fa_u per 2-row block + updw + pack init =========
__global__ void __launch_bounds__(1024, 1) k0(
    const float* __restrict__ inputs,
    const float* __restrict__ r_w1, const float* __restrict__ r_b1,
    const float* __restrict__ r_w2, const float* __restrict__ r_b2,
    const float* __restrict__ u_w1, const float* __restrict__ u_b1,
    const float* __restrict__ u_w2, const float* __restrict__ u_b2,
    const float* __restrict__ W_uw, const float* __restrict__ b_uw) {
    extern __shared__ u64 sh[];
    const int tid = threadIdx.x, bx = blockIdx.x;
    if (bx == 16) {
        if (tid < 48) g_s.pack[tid] = 0ull;
        return;
    }
    u64* xs_in = sh;
    u64* xsh = sh + 512;
    u64* part = sh + 1024;           // 3840
    float* red = (float*)(sh + 4864);
    float* sinv = (float*)(sh + 4868);

    const int fu = bx >> 3;
    const int r0 = (bx & 7) * 2;

    if (tid < 512)
        xs_in[tid] = packf2(__ldg(inputs + r0 * 512 + tid),
                            __ldg(inputs + (r0 + 1) * 512 + tid));
    u64 a[4]; int j;
    bool own = bgemm<4, 8, 512, 512, 8>(xs_in, fu ? u_w1 : r_w1, a, part, j);
    epi_exp<4>(own, a, j, fu ? u_b1 : r_b1, xsh, red, sinv);
    own = bgemm<4, 8, 512, 512, 8>(xsh, fu ? u_w2 : r_w2, a, part, j);
    if (own) {
        float4 bv = __ldg((const float4*)((fu ? u_b2 : r_b2) + j));
        float bq[4] = {bv.x, bv.y, bv.z, bv.w};
        #pragma unroll
        for (int q = 0; q < 4; q++) {
            float vlo = lohi(a[q], 0) * sinv[0] + bq[q];
            float vhi = lohi(a[q], 1) * sinv[1] + bq[q];
            u64 xv = xs_in[j + q];
            float ylo = lohi(xv, 0) * vlo, yhi = lohi(xv, 1) * vhi;
            if (fu == 0) {
                g_s.yr[r0 * 512 + j + q] = ylo;
                g_s.yr[(r0 + 1) * 512 + j + q] = yhi;
            } else {
                xsh[j + q] = packf2(ylo, yhi);
            }
        }
    }
    if (fu == 1) {
        __syncthreads();
        const int w = tid >> 5, lane = tid & 31;
        if (w < 3) {
            u64 acc = 0ull;
            for (int k = lane; k < 512; k += 32)
                ffma2(acc, xsh[k], pack2(__ldg(W_uw + k * 3 + w)));
            #pragma unroll
            for (int o = 16; o; o >>= 1)
                acc = addf2(acc, __shfl_xor_sync(0xffffffffu, acc, o));
            if (lane == 0) {
                float bb = __ldg(b_uw + w);
                g_s.updw[r0 * 3 + w] = 1.f / (1.f + __expf(-(lohi(acc, 0) + bb)));
                g_s.updw[(r0 + 1) * 3 + w] = 1.f / (1.f + __expf(-(lohi(acc, 1) + bb)));
            }
        }
    }
}

// ================= K1: big read GEMM + fused max/argmax =================
__global__ void __launch_bounds__(512, 1) k1(const float* __restrict__ W,
                                             const float* __restrict__ bias) {
    extern __shared__ u64 shr[];
    u64* xs2 = shr;              // [k][pair] 512*8
    u64* part = shr + 4096;
    const int tid = threadIdx.x, bx = blockIdx.x;
    const int NB = gridDim.x;

    for (int idx = tid; idx < 4096; idx += 512) {
        int p = idx / 512, k = idx - p * 512;
        float lo = __ldcg(g_s.yr + (2 * p) * 512 + k);
        float hi = __ldcg(g_s.yr + (2 * p + 1) * 512 + k);
        xs2[k * 8 + p] = packf2(lo, hi);
    }
    __syncthreads();

    const int w = tid >> 5, lane = tid & 31;
    const int ts = w >> 2, kh = w & 3;
    const int base = 471 / NB, rem = 471 - base * NB;
    const int cnt = base + (bx < rem ? 1 : 0);
    const int start = bx * base + (bx < rem ? bx : rem);
    const bool act = ts < cnt;

    int isec = 0, j0 = 0, j1 = 0;
    long n0 = 0;
    bool v0 = false;
    u64 a0[8], a1[8];

    if (act) {
        int gtile = start + ts;
        isec = gtile / 157;
        int t = gtile - isec * 157;
        j0 = t * 64 + lane * 2; j1 = j0 + 1;
        v0 = j0 < 10000;
        n0 = (long)isec * 10000 + j0;
        #pragma unroll
        for (int p = 0; p < 8; p++) { a0[p] = 0ull; a1[p] = 0ull; }

        const float* W0 = W + (long)(kh * 128) * 30000;
        const u64* xk = xs2 + (kh * 128) * 8;
        #pragma unroll 1
        for (int it = 0; it < 128; it += 8) {
            float2 wv[8];
            #pragma unroll
            for (int u = 0; u < 8; u++)
                wv[u] = v0 ? __ldg((const float2*)(W0 + (long)u * 30000 + n0))
                           : make_float2(0.f, 0.f);
            #pragma unroll
            for (int u = 0; u < 8; u++) {
                u64 wa2 = pack2(wv[u].x), wb2 = pack2(wv[u].y);
                const u64* xp = xk + u * 8;
                #pragma unroll
                for (int p = 0; p < 8; p++) {
                    u64 xv = xp[p];
                    ffma2(a0[p], xv, wa2);
                    ffma2(a1[p], xv, wb2);
                }
            }
            W0 += 8L * 30000; xk += 64;
        }
        if (kh > 0) {
            u64* ps = part + ((ts * 3 + (kh - 1)) * 32 + lane) * 16;
            #pragma unroll
            for (int p = 0; p < 8; p++) { ps[p] = a0[p]; ps[8 + p] = a1[p]; }
        }
    }
    __syncthreads();

    if (act && kh == 0) {
        #pragma unroll
        for (int h = 0; h < 3; h++) {
            const u64* ps = part + ((ts * 3 + h) * 32 + lane) * 16;
            #pragma unroll
            for (int p = 0; p < 8; p++) {
                a0[p] = addf2(a0[p], ps[p]);
                a1[p] = addf2(a1[p], ps[8 + p]);
            }
        }
        float2 bv = v0 ? __ldg((const float2*)(bias + n0)) : make_float2(0.f, 0.f);
        #pragma unroll
        for (int b = 0; b < 16; b++) {
            float z0 = lohi(a0[b >> 1], b & 1) + bv.x;
            float z1 = lohi(a1[b >> 1], b & 1) + bv.y;
            u64 c0 = v0 ? (((u64)forder(z0) << 32) | (u64)(0xFFFFFFFFu - (unsigned)j0)) : 0ull;
            u64 c1 = v0 ? (((u64)forder(z1) << 32) | (u64)(0xFFFFFFFFu - (unsigned)j1)) : 0ull;
            u64 c = c0 > c1 ? c0 : c1;
            #pragma unroll
            for (int o = 16; o; o >>= 1) {
                u64 q = __shfl_xor_sync(0xffffffffu, c, o);
                if (q > c) c = q;
            }
            if (lane == 0) atomicMax(&g_s.pack[b * 3 + isec], c);
        }
    }
}

// ================= K2: fa_um + r-update, 2-CTA cluster per (i, row pair) ==========
__global__ void __launch_bounds__(1024, 1) __cluster_dims__(2, 1, 1) k2(
    const float* __restrict__ inputs, const float* __restrict__ memory,
    const float* __restrict__ um_w1, const float* __restrict__ um_b1,
    const float* __restrict__ um_w2, const float* __restrict__ um_b2,
    const float* __restrict__ W_um, const float* __restrict__ b_um) {
    extern __shared__ u64 sh[];
    u64* cat = sh;                   // 768
    u64* e = sh + 768;               // 768 exp values
    u64* yv = sh + 1536;             // 768 yum values
    u64* part = sh + 2304;           // 2944
    float* red = (float*)(sh + 5248);   // 6 floats
    float* ps = (float*)(sh + 5251);    // 4 floats [rank*2 + row]
    float* sinv = (float*)(sh + 5253);  // 2 floats
    __shared__ long rowoff[2];
    __shared__ float su[2];

    const int tid = threadIdx.x;
    uint32_t rank;
    asm("mov.u32 %0, %%cluster_ctarank;" : "=r"(rank));
    const uint32_t peer = rank ^ 1u;
    const int cid = blockIdx.x >> 1;
    const int i = cid >> 3;
    const int r0 = (cid & 7) * 2;

    if (tid < 2) {
        u64 p = __ldcg(&g_s.pack[(r0 + tid) * 3 + i]);
        unsigned idx = 0xFFFFFFFFu - (unsigned)(p & 0xFFFFFFFFull);
        rowoff[tid] = ((long)(r0 + tid) * 10000 + idx) * 256;
        su[tid] = __ldcg(&g_s.updw[(r0 + tid) * 3 + i]);
    }
    __syncthreads();
    if (tid < 768) {
        float lo, hi;
        if (tid < 256) {
            lo = __ldg(memory + rowoff[0] + tid);
            hi = __ldg(memory + rowoff[1] + tid);
        } else {
            lo = __ldg(inputs + r0 * 512 + (tid - 256));
            hi = __ldg(inputs + (r0 + 1) * 512 + (tid - 256));
        }
        cat[tid] = packf2(lo, hi);
    }

    u64 a[4]; int j;
    // ---- GEMM1: h = cat @ um_w1[:, rank*384+..], exp -> e (own + peer) ----
    bool own = bgemm<3, 8, 768, 768, 8>(cat, um_w1 + rank * 384, a, part, j);
    {
        const int w = tid >> 5, lane = tid & 31;
        if (own) {
            int gj = rank * 384 + j;
            float4 bv = __ldg((const float4*)(um_b1 + gj));
            float bq[4] = {bv.x, bv.y, bv.z, bv.w};
            float sl = 0.f, sh2 = 0.f;
            #pragma unroll
            for (int q = 0; q < 4; q++) {
                float lo = __expf(lohi(a[q], 0) + bq[q]);
                float hi = __expf(lohi(a[q], 1) + bq[q]);
                u64 v = packf2(lo, hi);
                e[gj + q] = v;
                dsmem_st64(smem_u32(&e[gj + q]), peer, v);
                sl += lo; sh2 += hi;
            }
            #pragma unroll
            for (int o = 16; o; o >>= 1) {
                sl += __shfl_xor_sync(0xffffffffu, sl, o);
                sh2 += __shfl_xor_sync(0xffffffffu, sh2, o);
            }
            if (lane == 0) { red[w * 2] = sl; red[w * 2 + 1] = sh2; }
        }
        __syncthreads();
        if (tid < 2) {
            float s = red[tid] + red[2 + tid] + red[4 + tid];
            ps[rank * 2 + tid] = s;
            dsmem_stf(smem_u32(&ps[rank * 2 + tid]), peer, s);
        }
    }
    CLUSTER_SYNC();
    if (tid < 2) sinv[tid] = 1.f / (ps[tid] + ps[2 + tid]);

    // ---- GEMM2: y = cat * (softmax @ um_w2 + b) -> yv (own + peer) ----
    own = bgemm<3, 8, 768, 768, 8>(e, um_w2 + rank * 384, a, part, j);
    if (own) {
        int gj = rank * 384 + j;
        float4 bv = __ldg((const float4*)(um_b2 + gj));
        float bq[4] = {bv.x, bv.y, bv.z, bv.w};
        #pragma unroll
        for (int q = 0; q < 4; q++) {
            float vlo = lohi(a[q], 0) * sinv[0] + bq[q];
            float vhi = lohi(a[q], 1) * sinv[1] + bq[q];
            u64 cv = cat[gj + q];
            u64 y = packf2(lohi(cv, 0) * vlo, lohi(cv, 1) * vhi);
            yv[gj + q] = y;
            dsmem_st64(smem_u32(&yv[gj + q]), peer, y);
        }
    }
    CLUSTER_SYNC();

    // ---- GEMM3: rc = u*relu(yv@W_um + b) + (1-u)*r -> global (no exchange) ----
    own = bgemm<1, 24, 768, 256, 8>(yv, W_um + rank * 128, a, part, j);
    if (own) {
        int gj = rank * 128 + j;
        float4 bv = __ldg((const float4*)(b_um + gj));
        float bq[4] = {bv.x, bv.y, bv.z, bv.w};
        float ulo = su[0], uhi = su[1];
        #pragma unroll
        for (int q = 0; q < 4; q++) {
            float vlo = fmaxf(lohi(a[q], 0) + bq[q], 0.f);
            float vhi = fmaxf(lohi(a[q], 1) + bq[q], 0.f);
            u64 rv = cat[gj + q];
            g_s.rc[i][r0 * 256 + gj + q] = ulo * vlo + (1.f - ulo) * lohi(rv, 0);
            g_s.rc[i][(r0 + 1) * 256 + gj + q] = uhi * vhi + (1.f - uhi) * lohi(rv, 1);
        }
    }
}

// ================= K3: recurrent loop, 2 rows per 4-CTA cluster (j-split) =========
__global__ void __launch_bounds__(1024, 1) __cluster_dims__(4, 1, 1) k3(
    const float* __restrict__ am_w1, const float* __restrict__ am_b1,
    const float* __restrict__ am_w2, const float* __restrict__ am_b2,
    const float* __restrict__ W_am, const float* __restrict__ b_am,
    float* __restrict__ out) {
    extern __shared__ u64 sh[];
    u64* A = sh;                     // 512: [rc(256) | m(256)]
    u64* B = sh + 512;               // 512: exp values
    u64* C = sh + 1024;              // 512: yam values
    u64* part = sh + 1536;           // 3968
    float* ps = (float*)(sh + 5504);    // 8 floats [rank*2 + row]
    float* sinv = (float*)(sh + 5508);  // 2 floats
    __shared__ float srw[6];

    const int tid = threadIdx.x, lane = tid & 31;
    uint32_t rank;
    asm("mov.u32 %0, %%cluster_ctarank;" : "=r"(rank));
    const int r0 = (blockIdx.x >> 2) * 2;

    if (tid < 6) {
        int rr = tid / 3, ii = tid - rr * 3;
        u64 p = __ldcg(&g_s.pack[(r0 + rr) * 3 + ii]);
        srw[tid] = tanhf(forder_inv((unsigned)(p >> 32)));
    }
    if (tid >= 256 && tid < 512) A[tid] = 0ull;   // m = 0

    u64 a[4]; u64 a2[2]; int j;
    for (int i = 0; i < 3; i++) {
        if (tid < 256)
            A[tid] = packf2(__ldcg(g_s.rc[i] + r0 * 256 + tid),
                            __ldcg(g_s.rc[i] + (r0 + 1) * 256 + tid));
        // ---- GEMM1: h = A @ am_w1[:, rank*128+..], exp -> B (bcast) ----
        bool own = bgemm<1, 32, 512, 512, 8>(A, am_w1 + rank * 128, a, part, j);
        if (own) {
            int gj = rank * 128 + j;
            float4 bv = __ldg((const float4*)(am_b1 + gj));
            float bq[4] = {bv.x, bv.y, bv.z, bv.w};
            float sl = 0.f, sh2 = 0.f;
            #pragma unroll
            for (int q = 0; q < 4; q++) {
                float lo = __expf(lohi(a[q], 0) + bq[q]);
                float hi = __expf(lohi(a[q], 1) + bq[q]);
                u64 v = packf2(lo, hi);
                B[gj + q] = v;
                #pragma unroll
                for (uint32_t pr = 0; pr < 4; pr++)
                    if (pr != rank) dsmem_st64(smem_u32(&B[gj + q]), pr, v);
                sl += lo; sh2 += hi;
            }
            #pragma unroll
            for (int o = 16; o; o >>= 1) {
                sl += __shfl_xor_sync(0xffffffffu, sl, o);
                sh2 += __shfl_xor_sync(0xffffffffu, sh2, o);
            }
            if (lane == 0) {
                ps[rank * 2] = sl; ps[rank * 2 + 1] = sh2;
                #pragma unroll
                for (uint32_t pr = 0; pr < 4; pr++)
                    if (pr != rank) {
                        dsmem_stf(smem_u32(&ps[rank * 2]), pr, sl);
                        dsmem_stf(smem_u32(&ps[rank * 2 + 1]), pr, sh2);
                    }
            }
        }
        CLUSTER_SYNC();
        if (tid < 2)
            sinv[tid] = 1.f / (ps[tid] + ps[2 + tid] + ps[4 + tid] + ps[6 + tid]);
        // ---- GEMM2: y = A * (softmax @ am_w2 + b) -> C (bcast) ----
        own = bgemm<1, 32, 512, 512, 8>(B, am_w2 + rank * 128, a, part, j);
        if (own) {
            int gj = rank * 128 + j;
            float4 bv = __ldg((const float4*)(am_b2 + gj));
            float bq[4] = {bv.x, bv.y, bv.z, bv.w};
            #pragma unroll
            for (int q = 0; q < 4; q++) {
                float vlo = lohi(a[q], 0) * sinv[0] + bq[q];
                float vhi = lohi(a[q], 1) * sinv[1] + bq[q];
                u64 cv = A[gj + q];
                u64 y = packf2(lohi(cv, 0) * vlo, lohi(cv, 1) * vhi);
                C[gj + q] = y;
                #pragma unroll
                for (uint32_t pr = 0; pr < 4; pr++)
                    if (pr != rank) dsmem_st64(smem_u32(&C[gj + q]), pr, y);
            }
        }
        CLUSTER_SYNC();
        // ---- GEMM3: m = rw * relu(C @ W_am[:, rank*64+..] + b) -> A[256+] (bcast) ----
        bool own2 = bgemm2<32, 512, 256, 8>(C, W_am + rank * 64, a2, part, j);
        if (own2) {
            int gj = rank * 64 + j;   // j = lane*2
            float2 bv = __ldg((const float2*)(b_am + gj));
            float rwlo = srw[i], rwhi = srw[3 + i];
            float bq[2] = {bv.x, bv.y};
            #pragma unroll
            for (int q = 0; q < 2; q++) {
                float mlo = rwlo * fmaxf(lohi(a2[q], 0) + bq[q], 0.f);
                float mhi = rwhi * fmaxf(lohi(a2[q], 1) + bq[q], 0.f);
                u64 mv = packf2(mlo, mhi);
                A[256 + gj + q] = mv;
                #pragma unroll
                for (uint32_t pr = 0; pr < 4; pr++)
                    if (pr != rank) dsmem_st64(smem_u32(&A[256 + gj + q]), pr, mv);
                if (i == 2) {
                    out[r0 * 256 + gj + q] = tanhf(mlo);
                    out[(r0 + 1) * 256 + gj + q] = tanhf(mhi);
                }
            }
        }
        CLUSTER_SYNC();
    }
}

// ---------------- host launcher ----------------
extern "C" void kernel_launch(void* const* d_in, const int* in_sizes, int n_in,
                              void* d_out, int out_size) {
    const float* inputs = (const float*)d_in[0];
    const float* memory = (const float*)d_in[1];
    const float* r_w1 = (const float*)d_in[2];
    const float* r_b1 = (const float*)d_in[3];
    const float* r_w2 = (const float*)d_in[4];
    const float* r_b2 = (const float*)d_in[5];
    const float* W_read = (const float*)d_in[6];
    const float* b_read = (const float*)d_in[7];
    const float* u_w1 = (const float*)d_in[8];
    const float* u_b1 = (const float*)d_in[9];
    const float* u_w2 = (const float*)d_in[10];
    const float* u_b2 = (const float*)d_in[11];
    const float* W_uw = (const float*)d_in[12];
    const float* b_uw = (const float*)d_in[13];
    const float* um_w1 = (const float*)d_in[14];
    const float* um_b1 = (const float*)d_in[15];
    const float* um_w2 = (const float*)d_in[16];
    const float* um_b2 = (const float*)d_in[17];
    const float* W_um = (const float*)d_in[18];
    const float* b_um = (const float*)d_in[19];
    const float* am_w1 = (const float*)d_in[20];
    const float* am_b1 = (const float*)d_in[21];
    const float* am_w2 = (const float*)d_in[22];
    const float* am_b2 = (const float*)d_in[23];
    const float* W_am = (const float*)d_in[24];
    const float* b_am = (const float*)d_in[25];
    float* out = (float*)d_out;

    static int NB = 0;
    if (NB == 0) {
        cudaDeviceGetAttribute(&NB, cudaDevAttrMultiProcessorCount, 0);
        if (NB <= 0) NB = 148;
    }
    const int DSM0 = 38976;   // k0: 4872 u64
    const int DSM1 = 81920;   // k1
    const int DSM2 = 42048;   // k2: 5254 u64
    const int DSM3 = 44080;   // k3: 5509 u64
    static bool attr_set = false;
    if (!attr_set) {
        cudaFuncSetAttribute(k0, cudaFuncAttributeMaxDynamicSharedMemorySize, DSM0);
        cudaFuncSetAttribute(k1, cudaFuncAttributeMaxDynamicSharedMemorySize, DSM1);
        cudaFuncSetAttribute(k2, cudaFuncAttributeMaxDynamicSharedMemorySize, DSM2);
        cudaFuncSetAttribute(k3, cudaFuncAttributeMaxDynamicSharedMemorySize, DSM3);
        attr_set = true;
    }

    k0<<<17, 1024, DSM0>>>(inputs, r_w1, r_b1, r_w2, r_b2,
                           u_w1, u_b1, u_w2, u_b2, W_uw, b_uw);
    k1<<<NB, 512, DSM1>>>(W_read, b_read);
    k2<<<48, 1024, DSM2>>>(inputs, memory, um_w1, um_b1, um_w2, um_b2, W_um, b_um);
    k3<<<32, 1024, DSM3>>>(am_w1, am_b1, am_w2, am_b2, W_am, b_am, out);
}

// round 14
// speedup vs baseline: 2.9610x; 1.0377x over previous
#include <cuda_runtime.h>
#include <cstdint>

typedef unsigned long long u64;

// ---------------- scratch (no allocations allowed) ----------------
struct Scratch {
    float yr[16 * 512];          // fa_r output rows
    float rc[3][16 * 256];       // precomputed updated r per read-slot
    float updw[48];              // sigmoid update weights [b*3+i]
    u64 pack[48];                // (orderable_max << 32 | ~idx)
};
__device__ Scratch g_s;
__device__ volatile unsigned g_flag[24];   // rc-ready counters [i*8 + pair]

__device__ __forceinline__ unsigned forder(float f) {
    unsigned u = __float_as_uint(f);
    return (u & 0x80000000u) ? ~u : (u | 0x80000000u);
}
__device__ __forceinline__ float forder_inv(unsigned u) {
    unsigned v = (u & 0x80000000u) ? (u & 0x7FFFFFFFu) : ~u;
    return __uint_as_float(v);
}
__device__ __forceinline__ u64 pack2(float f) {
    unsigned u = __float_as_uint(f);
    return ((u64)u << 32) | (u64)u;
}
__device__ __forceinline__ u64 packf2(float lo, float hi) {
    return ((u64)__float_as_uint(hi) << 32) | (u64)__float_as_uint(lo);
}
__device__ __forceinline__ void ffma2(u64& acc, u64 x, u64 w) {
    asm("fma.rn.f32x2 %0, %1, %2, %0;" : "+l"(acc) : "l"(x), "l"(w));
}
__device__ __forceinline__ u64 addf2(u64 a, u64 b) {
    u64 d;
    asm("add.rn.f32x2 %0, %1, %2;" : "=l"(d) : "l"(a), "l"(b));
    return d;
}
__device__ __forceinline__ float lohi(u64 v, int hi) {
    return __uint_as_float(hi ? (unsigned)(v >> 32) : (unsigned)v);
}
__device__ __forceinline__ uint32_t smem_u32(const void* p) {
    return (uint32_t)__cvta_generic_to_shared(p);
}
__device__ __forceinline__ void dsmem_st64(uint32_t laddr, uint32_t peer, u64 v) {
    uint32_t r;
    asm volatile("mapa.shared::cluster.u32 %0, %1, %2;" : "=r"(r) : "r"(laddr), "r"(peer));
    asm volatile("st.shared::cluster.b64 [%0], %1;" :: "r"(r), "l"(v) : "memory");
}
__device__ __forceinline__ void dsmem_stf(uint32_t laddr, uint32_t peer, float v) {
    uint32_t r;
    asm volatile("mapa.shared::cluster.u32 %0, %1, %2;" : "=r"(r) : "r"(laddr), "r"(peer));
    asm volatile("st.shared::cluster.f32 [%0], %1;" :: "r"(r), "f"(v) : "memory");
}
#define CLUSTER_SYNC() do { \
    asm volatile("barrier.cluster.arrive.aligned;" ::: "memory"); \
    asm volatile("barrier.cluster.wait.aligned;" ::: "memory"); } while (0)

// ---------- block GEMM (row-pair packed): warp (jt, ks); 128 cols per j-warp ----------
template <int NJW, int NK, int K, int N, int D>
__device__ __forceinline__ bool bgemm(const u64* __restrict__ xs2,
                                      const float* __restrict__ W,
                                      u64 (&a)[4], u64* part, int& jout) {
    const int tid = threadIdx.x, w = tid >> 5, lane = tid & 31;
    const int jt = w % NJW, ks = w / NJW;
    const bool act = w < NJW * NK;
    jout = jt * 128 + lane * 4;
    constexpr int KC = K / NK;
    __syncthreads();   // protects part + input buffers from previous stage
    #pragma unroll
    for (int q = 0; q < 4; q++) a[q] = 0ull;
    if (act) {
        const float* wp = W + (long)(ks * KC) * N + jout;
        const u64* xk = xs2 + ks * KC;
        #pragma unroll 1
        for (int t = 0; t < KC; t += D) {
            float4 wv[D];
            #pragma unroll
            for (int u = 0; u < D; u++)
                wv[u] = __ldg((const float4*)(wp + (long)u * N));
            #pragma unroll
            for (int u = 0; u < D; u++) {
                u64 xv = xk[u];
                ffma2(a[0], xv, pack2(wv[u].x));
                ffma2(a[1], xv, pack2(wv[u].y));
                ffma2(a[2], xv, pack2(wv[u].z));
                ffma2(a[3], xv, pack2(wv[u].w));
            }
            wp += (long)D * N; xk += D;
        }
        if (ks > 0) {
            u64* ps = part + (((ks - 1) * NJW + jt) * 32 + lane) * 4;
            #pragma unroll
            for (int q = 0; q < 4; q++) ps[q] = a[q];
        }
    }
    __syncthreads();
    if (act && ks == 0) {
        #pragma unroll
        for (int h = 0; h < NK - 1; h++) {
            const u64* ps = part + ((h * NJW + jt) * 32 + lane) * 4;
            #pragma unroll
            for (int q = 0; q < 4; q++) a[q] = addf2(a[q], ps[q]);
        }
    }
    return act && (ks == 0);
}

// ---------- narrow block GEMM: single j-warp covering 64 cols (float2 loads) ----------
template <int NK, int K, int N, int D>
__device__ __forceinline__ bool bgemm2(const u64* __restrict__ xs2,
                                       const float* __restrict__ W,
                                       u64 (&a)[2], u64* part, int& jout) {
    const int tid = threadIdx.x, w = tid >> 5, lane = tid & 31;
    const int ks = w;
    const bool act = w < NK;
    jout = lane * 2;
    constexpr int KC = K / NK;
    __syncthreads();
    a[0] = 0ull; a[1] = 0ull;
    if (act) {
        const float* wp = W + (long)(ks * KC) * N + jout;
        const u64* xk = xs2 + ks * KC;
        #pragma unroll 1
        for (int t = 0; t < KC; t += D) {
            float2 wv[D];
            #pragma unroll
            for (int u = 0; u < D; u++)
                wv[u] = __ldg((const float2*)(wp + (long)u * N));
            #pragma unroll
            for (int u = 0; u < D; u++) {
                u64 xv = xk[u];
                ffma2(a[0], xv, pack2(wv[u].x));
                ffma2(a[1], xv, pack2(wv[u].y));
            }
            wp += (long)D * N; xk += D;
        }
        if (ks > 0) {
            u64* ps = part + ((ks - 1) * 32 + lane) * 2;
            ps[0] = a[0]; ps[1] = a[1];
        }
    }
    __syncthreads();
    if (act && ks == 0) {
        #pragma unroll
        for (int h = 0; h < NK - 1; h++) {
            const u64* ps = part + (h * 32 + lane) * 2;
            a[0] = addf2(a[0], ps[0]);
            a[1] = addf2(a[1], ps[1]);
        }
    }
    return act && (ks == 0);
}

// ================= K0: fa_r / fa_u, 2-CTA cluster per row pair (j-split) ===========
__global__ void __launch_bounds__(1024, 1) __cluster_dims__(2, 1, 1) k0(
    const float* __restrict__ inputs,
    const float* __restrict__ r_w1, const float* __restrict__ r_b1,
    const float* __restrict__ r_w2, const float* __restrict__ r_b2,
    const float* __restrict__ u_w1, const float* __restrict__ u_b1,
    const float* __restrict__ u_w2, const float* __restrict__ u_b2,
    const float* __restrict__ W_uw, const float* __restrict__ b_uw) {
    extern __shared__ u64 sh[];
    u64* X = sh;                     // 512 packed input pair
    u64* H = sh + 512;               // 512 exp values (full after exchange)
    u64* Y = sh + 1024;              // 512 fa_u output (own cols only)
    u64* part = sh + 1536;           // 3840
    float* red = (float*)(sh + 5376);   // 4
    float* ps = (float*)(sh + 5378);    // 4
    float* sinv = (float*)(sh + 5380);  // 2
    float* pw = (float*)(sh + 5381);    // 12

    const int tid = threadIdx.x, bx = blockIdx.x;
    uint32_t rank;
    asm("mov.u32 %0, %%cluster_ctarank;" : "=r"(rank));
    const uint32_t peer = rank ^ 1u;
    const int fu = bx >> 4;          // 0 = fa_r, 1 = fa_u
    const int r0 = ((bx >> 1) & 7) * 2;

    if (bx == 0) {
        if (tid < 48) g_s.pack[tid] = 0ull;
        if (tid < 24) g_flag[tid] = 0u;
    }
    if (tid < 512)
        X[tid] = packf2(__ldg(inputs + r0 * 512 + tid),
                        __ldg(inputs + (r0 + 1) * 512 + tid));

    u64 a[4]; int j;
    // stage 1: h = x@w1, exp -> H (own half + exchange)
    bool own = bgemm<2, 16, 512, 512, 8>(X, (fu ? u_w1 : r_w1) + rank * 256, a, part, j);
    {
        const int w = tid >> 5, lane = tid & 31;
        if (own) {
            int gj = rank * 256 + j;
            float4 bv = __ldg((const float4*)((fu ? u_b1 : r_b1) + gj));
            float bq[4] = {bv.x, bv.y, bv.z, bv.w};
            float sl = 0.f, sh2 = 0.f;
            #pragma unroll
            for (int q = 0; q < 4; q++) {
                float lo = __expf(lohi(a[q], 0) + bq[q]);
                float hi = __expf(lohi(a[q], 1) + bq[q]);
                u64 v = packf2(lo, hi);
                H[gj + q] = v;
                dsmem_st64(smem_u32(&H[gj + q]), peer, v);
                sl += lo; sh2 += hi;
            }
            #pragma unroll
            for (int o = 16; o; o >>= 1) {
                sl += __shfl_xor_sync(0xffffffffu, sl, o);
                sh2 += __shfl_xor_sync(0xffffffffu, sh2, o);
            }
            if (lane == 0) { red[w * 2] = sl; red[w * 2 + 1] = sh2; }
        }
        __syncthreads();
        if (tid < 2) {
            float s = red[tid] + red[2 + tid];
            ps[rank * 2 + tid] = s;
            dsmem_stf(smem_u32(&ps[rank * 2 + tid]), peer, s);
        }
    }
    CLUSTER_SYNC();
    if (tid < 2) sinv[tid] = 1.f / (ps[tid] + ps[2 + tid]);

    // stage 2: y = x * (softmax @ w2 + b)
    own = bgemm<2, 16, 512, 512, 8>(H, (fu ? u_w2 : r_w2) + rank * 256, a, part, j);
    if (own) {
        int gj = rank * 256 + j;
        float4 bv = __ldg((const float4*)((fu ? u_b2 : r_b2) + gj));
        float bq[4] = {bv.x, bv.y, bv.z, bv.w};
        #pragma unroll
        for (int q = 0; q < 4; q++) {
            float vlo = lohi(a[q], 0) * sinv[0] + bq[q];
            float vhi = lohi(a[q], 1) * sinv[1] + bq[q];
            u64 xv = X[gj + q];
            float ylo = lohi(xv, 0) * vlo, yhi = lohi(xv, 1) * vhi;
            if (fu == 0) {
                g_s.yr[r0 * 512 + gj + q] = ylo;
                g_s.yr[(r0 + 1) * 512 + gj + q] = yhi;
            } else {
                Y[gj + q] = packf2(ylo, yhi);
            }
        }
    }
    if (fu == 1) {
        __syncthreads();
        const int w = tid >> 5, lane = tid & 31;
        if (w < 3) {   // partial updw dot over own 256 k
            u64 acc = 0ull;
            int kbase = rank * 256;
            for (int k = lane; k < 256; k += 32)
                ffma2(acc, Y[kbase + k], pack2(__ldg(W_uw + (kbase + k) * 3 + w)));
            #pragma unroll
            for (int o = 16; o; o >>= 1)
                acc = addf2(acc, __shfl_xor_sync(0xffffffffu, acc, o));
            if (lane == 0) {
                float plo = lohi(acc, 0), phi = lohi(acc, 1);
                pw[rank * 6 + w * 2] = plo;
                pw[rank * 6 + w * 2 + 1] = phi;
                dsmem_stf(smem_u32(&pw[rank * 6 + w * 2]), peer, plo);
                dsmem_stf(smem_u32(&pw[rank * 6 + w * 2 + 1]), peer, phi);
            }
        }
        CLUSTER_SYNC();
        if (rank == 0 && tid < 6) {
            int w2 = tid >> 1, row = tid & 1;
            float s = pw[w2 * 2 + row] + pw[6 + w2 * 2 + row] + __ldg(b_uw + w2);
            g_s.updw[(r0 + row) * 3 + w2] = 1.f / (1.f + __expf(-s));
        }
    } else {
        CLUSTER_SYNC();
    }
}

// ================= K1: big read GEMM + fused max/argmax (unchanged) =================
__global__ void __launch_bounds__(512, 1) k1(const float* __restrict__ W,
                                             const float* __restrict__ bias) {
    extern __shared__ u64 shr[];
    u64* xs2 = shr;
    u64* part = shr + 4096;
    const int tid = threadIdx.x, bx = blockIdx.x;
    const int NB = gridDim.x;

    for (int idx = tid; idx < 4096; idx += 512) {
        int p = idx / 512, k = idx - p * 512;
        float lo = __ldcg(g_s.yr + (2 * p) * 512 + k);
        float hi = __ldcg(g_s.yr + (2 * p + 1) * 512 + k);
        xs2[k * 8 + p] = packf2(lo, hi);
    }
    __syncthreads();

    const int w = tid >> 5, lane = tid & 31;
    const int ts = w >> 2, kh = w & 3;
    const int base = 471 / NB, rem = 471 - base * NB;
    const int cnt = base + (bx < rem ? 1 : 0);
    const int start = bx * base + (bx < rem ? bx : rem);
    const bool act = ts < cnt;

    int isec = 0, j0 = 0, j1 = 0;
    long n0 = 0;
    bool v0 = false;
    u64 a0[8], a1[8];

    if (act) {
        int gtile = start + ts;
        isec = gtile / 157;
        int t = gtile - isec * 157;
        j0 = t * 64 + lane * 2; j1 = j0 + 1;
        v0 = j0 < 10000;
        n0 = (long)isec * 10000 + j0;
        #pragma unroll
        for (int p = 0; p < 8; p++) { a0[p] = 0ull; a1[p] = 0ull; }

        const float* W0 = W + (long)(kh * 128) * 30000;
        const u64* xk = xs2 + (kh * 128) * 8;
        #pragma unroll 1
        for (int it = 0; it < 128; it += 8) {
            float2 wv[8];
            #pragma unroll
            for (int u = 0; u < 8; u++)
                wv[u] = v0 ? __ldg((const float2*)(W0 + (long)u * 30000 + n0))
                           : make_float2(0.f, 0.f);
            #pragma unroll
            for (int u = 0; u < 8; u++) {
                u64 wa2 = pack2(wv[u].x), wb2 = pack2(wv[u].y);
                const u64* xp = xk + u * 8;
                #pragma unroll
                for (int p = 0; p < 8; p++) {
                    u64 xv = xp[p];
                    ffma2(a0[p], xv, wa2);
                    ffma2(a1[p], xv, wb2);
                }
            }
            W0 += 8L * 30000; xk += 64;
        }
        if (kh > 0) {
            u64* ps = part + ((ts * 3 + (kh - 1)) * 32 + lane) * 16;
            #pragma unroll
            for (int p = 0; p < 8; p++) { ps[p] = a0[p]; ps[8 + p] = a1[p]; }
        }
    }
    __syncthreads();

    if (act && kh == 0) {
        #pragma unroll
        for (int h = 0; h < 3; h++) {
            const u64* ps = part + ((ts * 3 + h) * 32 + lane) * 16;
            #pragma unroll
            for (int p = 0; p < 8; p++) {
                a0[p] = addf2(a0[p], ps[p]);
                a1[p] = addf2(a1[p], ps[8 + p]);
            }
        }
        float2 bv = v0 ? __ldg((const float2*)(bias + n0)) : make_float2(0.f, 0.f);
        #pragma unroll
        for (int b = 0; b < 16; b++) {
            float z0 = lohi(a0[b >> 1], b & 1) + bv.x;
            float z1 = lohi(a1[b >> 1], b & 1) + bv.y;
            u64 c0 = v0 ? (((u64)forder(z0) << 32) | (u64)(0xFFFFFFFFu - (unsigned)j0)) : 0ull;
            u64 c1 = v0 ? (((u64)forder(z1) << 32) | (u64)(0xFFFFFFFFu - (unsigned)j1)) : 0ull;
            u64 c = c0 > c1 ? c0 : c1;
            #pragma unroll
            for (int o = 16; o; o >>= 1) {
                u64 q = __shfl_xor_sync(0xffffffffu, c, o);
                if (q > c) c = q;
            }
            if (lane == 0) atomicMax(&g_s.pack[b * 3 + isec], c);
        }
    }
}

// ---------------- k2 role: fa_um + r-update for task t (sub-pair inside cluster) ----
__device__ void k2_role(u64* sh, int t, uint32_t rank,
                        const float* __restrict__ inputs, const float* __restrict__ memory,
                        const float* __restrict__ um_w1, const float* __restrict__ um_b1,
                        const float* __restrict__ um_w2, const float* __restrict__ um_b2,
                        const float* __restrict__ W_um, const float* __restrict__ b_um) {
    u64* cat = sh;                   // 768
    u64* e = sh + 768;               // 768
    u64* yv = sh + 1536;             // 768
    u64* part = sh + 2304;           // 2944
    float* red = (float*)(sh + 5248);   // 6
    float* ps = (float*)(sh + 5251);    // 4
    float* sinv = (float*)(sh + 5253);  // 2
    __shared__ long rowoff[2];
    __shared__ float su[2];

    const int tid = threadIdx.x;
    const uint32_t sr = rank & 1u;
    const uint32_t peer = rank ^ 1u;
    const int i = t >> 3;
    const int r0 = (t & 7) * 2;

    if (tid < 2) {
        u64 p = __ldcg(&g_s.pack[(r0 + tid) * 3 + i]);
        unsigned idx = 0xFFFFFFFFu - (unsigned)(p & 0xFFFFFFFFull);
        rowoff[tid] = ((long)(r0 + tid) * 10000 + idx) * 256;
        su[tid] = __ldcg(&g_s.updw[(r0 + tid) * 3 + i]);
    }
    __syncthreads();
    if (tid < 768) {
        float lo, hi;
        if (tid < 256) {
            lo = __ldg(memory + rowoff[0] + tid);
            hi = __ldg(memory + rowoff[1] + tid);
        } else {
            lo = __ldg(inputs + r0 * 512 + (tid - 256));
            hi = __ldg(inputs + (r0 + 1) * 512 + (tid - 256));
        }
        cat[tid] = packf2(lo, hi);
    }

    u64 a[4]; int j;
    bool own = bgemm<3, 8, 768, 768, 8>(cat, um_w1 + sr * 384, a, part, j);
    {
        const int w = tid >> 5, lane = tid & 31;
        if (own) {
            int gj = sr * 384 + j;
            float4 bv = __ldg((const float4*)(um_b1 + gj));
            float bq[4] = {bv.x, bv.y, bv.z, bv.w};
            float sl = 0.f, sh2 = 0.f;
            #pragma unroll
            for (int q = 0; q < 4; q++) {
                float lo = __expf(lohi(a[q], 0) + bq[q]);
                float hi = __expf(lohi(a[q], 1) + bq[q]);
                u64 v = packf2(lo, hi);
                e[gj + q] = v;
                dsmem_st64(smem_u32(&e[gj + q]), peer, v);
                sl += lo; sh2 += hi;
            }
            #pragma unroll
            for (int o = 16; o; o >>= 1) {
                sl += __shfl_xor_sync(0xffffffffu, sl, o);
                sh2 += __shfl_xor_sync(0xffffffffu, sh2, o);
            }
            if (lane == 0) { red[w * 2] = sl; red[w * 2 + 1] = sh2; }
        }
        __syncthreads();
        if (tid < 2) {
            float s = red[tid] + red[2 + tid] + red[4 + tid];
            ps[sr * 2 + tid] = s;
            dsmem_stf(smem_u32(&ps[sr * 2 + tid]), peer, s);
        }
    }
    CLUSTER_SYNC();
    if (tid < 2) sinv[tid] = 1.f / (ps[tid] + ps[2 + tid]);

    own = bgemm<3, 8, 768, 768, 8>(e, um_w2 + sr * 384, a, part, j);
    if (own) {
        int gj = sr * 384 + j;
        float4 bv = __ldg((const float4*)(um_b2 + gj));
        float bq[4] = {bv.x, bv.y, bv.z, bv.w};
        #pragma unroll
        for (int q = 0; q < 4; q++) {
            float vlo = lohi(a[q], 0) * sinv[0] + bq[q];
            float vhi = lohi(a[q], 1) * sinv[1] + bq[q];
            u64 cv = cat[gj + q];
            u64 y = packf2(lohi(cv, 0) * vlo, lohi(cv, 1) * vhi);
            yv[gj + q] = y;
            dsmem_st64(smem_u32(&yv[gj + q]), peer, y);
        }
    }
    CLUSTER_SYNC();

    own = bgemm<1, 24, 768, 256, 8>(yv, W_um + sr * 128, a, part, j);
    if (own) {
        int gj = sr * 128 + j;
        float4 bv = __ldg((const float4*)(b_um + gj));
        float bq[4] = {bv.x, bv.y, bv.z, bv.w};
        float ulo = su[0], uhi = su[1];
        #pragma unroll
        for (int q = 0; q < 4; q++) {
            float vlo = fmaxf(lohi(a[q], 0) + bq[q], 0.f);
            float vhi = fmaxf(lohi(a[q], 1) + bq[q], 0.f);
            u64 rv = cat[gj + q];
            g_s.rc[i][r0 * 256 + gj + q] = ulo * vlo + (1.f - ulo) * lohi(rv, 0);
            g_s.rc[i][(r0 + 1) * 256 + gj + q] = uhi * vhi + (1.f - uhi) * lohi(rv, 1);
        }
    }
    __syncthreads();
    if (tid == 0) {
        __threadfence();
        atomicAdd((unsigned*)&g_flag[i * 8 + (t & 7)], 1u);
    }
}

// ---------------- k3 role: recurrent loop, 2 rows per 4-CTA cluster -----------------
__device__ void k3_role(u64* sh, int pair, uint32_t rank,
                        const float* __restrict__ am_w1, const float* __restrict__ am_b1,
                        const float* __restrict__ am_w2, const float* __restrict__ am_b2,
                        const float* __restrict__ W_am, const float* __restrict__ b_am,
                        float* __restrict__ out) {
    u64* A = sh;                     // 512: [rc(256) | m(256)]
    u64* B = sh + 512;               // 512
    u64* C = sh + 1024;              // 512
    u64* part = sh + 1536;           // 3968
    float* ps = (float*)(sh + 5504);    // 8
    float* sinv = (float*)(sh + 5508);  // 2
    __shared__ float srw[6];

    const int tid = threadIdx.x, lane = tid & 31;
    const int r0 = pair * 2;

    if (tid < 6) {
        int rr = tid / 3, ii = tid - rr * 3;
        u64 p = __ldcg(&g_s.pack[(r0 + rr) * 3 + ii]);
        srw[tid] = tanhf(forder_inv((unsigned)(p >> 32)));
    }
    if (tid >= 256 && tid < 512) A[tid] = 0ull;   // m = 0

    u64 a[4]; u64 a2[2]; int j;
    for (int i = 0; i < 3; i++) {
        if (tid == 0) {
            while (g_flag[i * 8 + pair] < 2u) { }
            __threadfence();
        }
        __syncthreads();
        if (tid < 256)
            A[tid] = packf2(__ldcg(g_s.rc[i] + r0 * 256 + tid),
                            __ldcg(g_s.rc[i] + (r0 + 1) * 256 + tid));
        // GEMM1: exp(A @ am_w1) -> B (broadcast)
        bool own = bgemm<1, 32, 512, 512, 8>(A, am_w1 + rank * 128, a, part, j);
        if (own) {
            int gj = rank * 128 + j;
            float4 bv = __ldg((const float4*)(am_b1 + gj));
            float bq[4] = {bv.x, bv.y, bv.z, bv.w};
            float sl = 0.f, sh2 = 0.f;
            #pragma unroll
            for (int q = 0; q < 4; q++) {
                float lo = __expf(lohi(a[q], 0) + bq[q]);
                float hi = __expf(lohi(a[q], 1) + bq[q]);
                u64 v = packf2(lo, hi);
                B[gj + q] = v;
                #pragma unroll
                for (uint32_t pr = 0; pr < 4; pr++)
                    if (pr != rank) dsmem_st64(smem_u32(&B[gj + q]), pr, v);
                sl += lo; sh2 += hi;
            }
            #pragma unroll
            for (int o = 16; o; o >>= 1) {
                sl += __shfl_xor_sync(0xffffffffu, sl, o);
                sh2 += __shfl_xor_sync(0xffffffffu, sh2, o);
            }
            if (lane == 0) {
                ps[rank * 2] = sl; ps[rank * 2 + 1] = sh2;
                #pragma unroll
                for (uint32_t pr = 0; pr < 4; pr++)
                    if (pr != rank) {
                        dsmem_stf(smem_u32(&ps[rank * 2]), pr, sl);
                        dsmem_stf(smem_u32(&ps[rank * 2 + 1]), pr, sh2);
                    }
            }
        }
        CLUSTER_SYNC();
        if (tid < 2)
            sinv[tid] = 1.f / (ps[tid] + ps[2 + tid] + ps[4 + tid] + ps[6 + tid]);
        // GEMM2: y = A * (softmax @ am_w2 + b) -> C (broadcast)
        own = bgemm<1, 32, 512, 512, 8>(B, am_w2 + rank * 128, a, part, j);
        if (own) {
            int gj = rank * 128 + j;
            float4 bv = __ldg((const float4*)(am_b2 + gj));
            float bq[4] = {bv.x, bv.y, bv.z, bv.w};
            #pragma unroll
            for (int q = 0; q < 4; q++) {
                float vlo = lohi(a[q], 0) * sinv[0] + bq[q];
                float vhi = lohi(a[q], 1) * sinv[1] + bq[q];
                u64 cv = A[gj + q];
                u64 y = packf2(lohi(cv, 0) * vlo, lohi(cv, 1) * vhi);
                C[gj + q] = y;
                #pragma unroll
                for (uint32_t pr = 0; pr < 4; pr++)
                    if (pr != rank) dsmem_st64(smem_u32(&C[gj + q]), pr, y);
            }
        }
        CLUSTER_SYNC();
        // GEMM3: m = rw * relu(C @ W_am + b) -> A[256+] (broadcast)
        bool own2 = bgemm2<32, 512, 256, 8>(C, W_am + rank * 64, a2, part, j);
        if (own2) {
            int gj = rank * 64 + j;
            float2 bv = __ldg((const float2*)(b_am + gj));
            float rwlo = srw[i], rwhi = srw[3 + i];
            float bq[2] = {bv.x, bv.y};
            #pragma unroll
            for (int q = 0; q < 2; q++) {
                float mlo = rwlo * fmaxf(lohi(a2[q], 0) + bq[q], 0.f);
                float mhi = rwhi * fmaxf(lohi(a2[q], 1) + bq[q], 0.f);
                u64 mv = packf2(mlo, mhi);
                A[256 + gj + q] = mv;
                #pragma unroll
                for (uint32_t pr = 0; pr < 4; pr++)
                    if (pr != rank) dsmem_st64(smem_u32(&A[256 + gj + q]), pr, mv);
                if (i == 2) {
                    out[r0 * 256 + gj + q] = tanhf(mlo);
                    out[(r0 + 1) * 256 + gj + q] = tanhf(mhi);
                }
            }
        }
        CLUSTER_SYNC();
    }
}

// ================= K23: fused k2 (producer) + k3 (consumer) =================
__global__ void __launch_bounds__(1024, 1) __cluster_dims__(4, 1, 1) k23(
    const float* __restrict__ inputs, const float* __restrict__ memory,
    const float* __restrict__ um_w1, const float* __restrict__ um_b1,
    const float* __restrict__ um_w2, const float* __restrict__ um_b2,
    const float* __restrict__ W_um, const float* __restrict__ b_um,
    const float* __restrict__ am_w1, const float* __restrict__ am_b1,
    const float* __restrict__ am_w2, const float* __restrict__ am_b2,
    const float* __restrict__ W_am, const float* __restrict__ b_am,
    float* __restrict__ out) {
    extern __shared__ u64 sh[];
    const int cid = blockIdx.x >> 2;
    uint32_t rank;
    asm("mov.u32 %0, %%cluster_ctarank;" : "=r"(rank));
    if (cid < 12) {
        int t = cid * 2 + (int)(rank >> 1);   // i-major: t = i*8 + pair
        k2_role(sh, t, rank, inputs, memory, um_w1, um_b1, um_w2, um_b2, W_um, b_um);
    } else {
        k3_role(sh, cid - 12, rank, am_w1, am_b1, am_w2, am_b2, W_am, b_am, out);
    }
}

// ---------------- host launcher ----------------
extern "C" void kernel_launch(void* const* d_in, const int* in_sizes, int n_in,
                              void* d_out, int out_size) {
    const float* inputs = (const float*)d_in[0];
    const float* memory = (const float*)d_in[1];
    const float* r_w1 = (const float*)d_in[2];
    const float* r_b1 = (const float*)d_in[3];
    const float* r_w2 = (const float*)d_in[4];
    const float* r_b2 = (const float*)d_in[5];
    const float* W_read = (const float*)d_in[6];
    const float* b_read = (const float*)d_in[7];
    const float* u_w1 = (const float*)d_in[8];
    const float* u_b1 = (const float*)d_in[9];
    const float* u_w2 = (const float*)d_in[10];
    const float* u_b2 = (const float*)d_in[11];
    const float* W_uw = (const float*)d_in[12];
    const float* b_uw = (const float*)d_in[13];
    const float* um_w1 = (const float*)d_in[14];
    const float* um_b1 = (const float*)d_in[15];
    const float* um_w2 = (const float*)d_in[16];
    const float* um_b2 = (const float*)d_in[17];
    const float* W_um = (const float*)d_in[18];
    const float* b_um = (const float*)d_in[19];
    const float* am_w1 = (const float*)d_in[20];
    const float* am_b1 = (const float*)d_in[21];
    const float* am_w2 = (const float*)d_in[22];
    const float* am_b2 = (const float*)d_in[23];
    const float* W_am = (const float*)d_in[24];
    const float* b_am = (const float*)d_in[25];
    float* out = (float*)d_out;

    static int NB = 0;
    if (NB == 0) {
        cudaDeviceGetAttribute(&NB, cudaDevAttrMultiProcessorCount, 0);
        if (NB <= 0) NB = 148;
    }
    const int DSM0 = 43200;   // k0: 5387 u64 (+pad)
    const int DSM1 = 81920;   // k1
    const int DSM23 = 44080;  // k23: max(k2 5254, k3 5509) u64
    static bool attr_set = false;
    if (!attr_set) {
        cudaFuncSetAttribute(k0,  cudaFuncAttributeMaxDynamicSharedMemorySize, DSM0);
        cudaFuncSetAttribute(k1,  cudaFuncAttributeMaxDynamicSharedMemorySize, DSM1);
        cudaFuncSetAttribute(k23, cudaFuncAttributeMaxDynamicSharedMemorySize, DSM23);
        attr_set = true;
    }

    k0<<<32, 1024, DSM0>>>(inputs, r_w1, r_b1, r_w2, r_b2,
                           u_w1, u_b1, u_w2, u_b2, W_uw, b_uw);
    k1<<<NB, 512, DSM1>>>(W_read, b_read);
    k23<<<80, 1024, DSM23>>>(inputs, memory, um_w1, um_b1, um_w2, um_b2,
                             W_um, b_um, am_w1, am_b1, am_w2, am_b2,
                             W_am, b_am, out);
}

// round 15
// speedup vs baseline: 3.1652x; 1.0690x over previous
#include <cuda_runtime.h>
#include <cstdint>

typedef unsigned long long u64;

// ---------------- scratch (no allocations allowed) ----------------
struct Scratch {
    float yr[16 * 512];          // fa_r output rows
    float rc[3][16 * 256];       // precomputed updated r per read-slot
    float updw[48];              // sigmoid update weights [b*3+i]
    u64 pack[48];                // (orderable_max << 32 | ~idx)
};
__device__ Scratch g_s;
__device__ volatile unsigned g_flag[24];   // rc-ready counters [i*8 + pair]

__device__ __forceinline__ unsigned forder(float f) {
    unsigned u = __float_as_uint(f);
    return (u & 0x80000000u) ? ~u : (u | 0x80000000u);
}
__device__ __forceinline__ float forder_inv(unsigned u) {
    unsigned v = (u & 0x80000000u) ? (u & 0x7FFFFFFFu) : ~u;
    return __uint_as_float(v);
}
__device__ __forceinline__ u64 pack2(float f) {
    unsigned u = __float_as_uint(f);
    return ((u64)u << 32) | (u64)u;
}
__device__ __forceinline__ u64 packf2(float lo, float hi) {
    return ((u64)__float_as_uint(hi) << 32) | (u64)__float_as_uint(lo);
}
__device__ __forceinline__ void ffma2(u64& acc, u64 x, u64 w) {
    asm("fma.rn.f32x2 %0, %1, %2, %0;" : "+l"(acc) : "l"(x), "l"(w));
}
__device__ __forceinline__ u64 addf2(u64 a, u64 b) {
    u64 d;
    asm("add.rn.f32x2 %0, %1, %2;" : "=l"(d) : "l"(a), "l"(b));
    return d;
}
__device__ __forceinline__ float lohi(u64 v, int hi) {
    return __uint_as_float(hi ? (unsigned)(v >> 32) : (unsigned)v);
}
__device__ __forceinline__ uint32_t smem_u32(const void* p) {
    return (uint32_t)__cvta_generic_to_shared(p);
}
__device__ __forceinline__ void dsmem_st64(uint32_t laddr, uint32_t peer, u64 v) {
    uint32_t r;
    asm volatile("mapa.shared::cluster.u32 %0, %1, %2;" : "=r"(r) : "r"(laddr), "r"(peer));
    asm volatile("st.shared::cluster.b64 [%0], %1;" :: "r"(r), "l"(v) : "memory");
}
__device__ __forceinline__ void dsmem_stf(uint32_t laddr, uint32_t peer, float v) {
    uint32_t r;
    asm volatile("mapa.shared::cluster.u32 %0, %1, %2;" : "=r"(r) : "r"(laddr), "r"(peer));
    asm volatile("st.shared::cluster.f32 [%0], %1;" :: "r"(r), "f"(v) : "memory");
}
#define CLUSTER_SYNC() do { \
    asm volatile("barrier.cluster.arrive.aligned;" ::: "memory"); \
    asm volatile("barrier.cluster.wait.aligned;" ::: "memory"); } while (0)

// ---------- block GEMM (row-pair packed): warp (jt, ks); 128 cols per j-warp ----------
template <int NJW, int NK, int K, int N, int D>
__device__ __forceinline__ bool bgemm(const u64* __restrict__ xs2,
                                      const float* __restrict__ W,
                                      u64 (&a)[4], u64* part, int& jout) {
    const int tid = threadIdx.x, w = tid >> 5, lane = tid & 31;
    const int jt = w % NJW, ks = w / NJW;
    const bool act = w < NJW * NK;
    jout = jt * 128 + lane * 4;
    constexpr int KC = K / NK;
    __syncthreads();   // protects part + input buffers from previous stage
    #pragma unroll
    for (int q = 0; q < 4; q++) a[q] = 0ull;
    if (act) {
        const float* wp = W + (long)(ks * KC) * N + jout;
        const u64* xk = xs2 + ks * KC;
        #pragma unroll 1
        for (int t = 0; t < KC; t += D) {
            float4 wv[D];
            #pragma unroll
            for (int u = 0; u < D; u++)
                wv[u] = __ldg((const float4*)(wp + (long)u * N));
            #pragma unroll
            for (int u = 0; u < D; u++) {
                u64 xv = xk[u];
                ffma2(a[0], xv, pack2(wv[u].x));
                ffma2(a[1], xv, pack2(wv[u].y));
                ffma2(a[2], xv, pack2(wv[u].z));
                ffma2(a[3], xv, pack2(wv[u].w));
            }
            wp += (long)D * N; xk += D;
        }
        if (ks > 0) {
            u64* ps = part + (((ks - 1) * NJW + jt) * 32 + lane) * 4;
            #pragma unroll
            for (int q = 0; q < 4; q++) ps[q] = a[q];
        }
    }
    __syncthreads();
    if (act && ks == 0) {
        #pragma unroll
        for (int h = 0; h < NK - 1; h++) {
            const u64* ps = part + ((h * NJW + jt) * 32 + lane) * 4;
            #pragma unroll
            for (int q = 0; q < 4; q++) a[q] = addf2(a[q], ps[q]);
        }
    }
    return act && (ks == 0);
}

// ---------- narrow block GEMM: single j-warp covering 64 cols (float2 loads) ----------
template <int NK, int K, int N, int D>
__device__ __forceinline__ bool bgemm2(const u64* __restrict__ xs2,
                                       const float* __restrict__ W,
                                       u64 (&a)[2], u64* part, int& jout) {
    const int tid = threadIdx.x, w = tid >> 5, lane = tid & 31;
    const int ks = w;
    const bool act = w < NK;
    jout = lane * 2;
    constexpr int KC = K / NK;
    __syncthreads();
    a[0] = 0ull; a[1] = 0ull;
    if (act) {
        const float* wp = W + (long)(ks * KC) * N + jout;
        const u64* xk = xs2 + ks * KC;
        #pragma unroll 1
        for (int t = 0; t < KC; t += D) {
            float2 wv[D];
            #pragma unroll
            for (int u = 0; u < D; u++)
                wv[u] = __ldg((const float2*)(wp + (long)u * N));
            #pragma unroll
            for (int u = 0; u < D; u++) {
                u64 xv = xk[u];
                ffma2(a[0], xv, pack2(wv[u].x));
                ffma2(a[1], xv, pack2(wv[u].y));
            }
            wp += (long)D * N; xk += D;
        }
        if (ks > 0) {
            u64* ps = part + ((ks - 1) * 32 + lane) * 2;
            ps[0] = a[0]; ps[1] = a[1];
        }
    }
    __syncthreads();
    if (act && ks == 0) {
        #pragma unroll
        for (int h = 0; h < NK - 1; h++) {
            const u64* ps = part + (h * 32 + lane) * 2;
            a[0] = addf2(a[0], ps[0]);
            a[1] = addf2(a[1], ps[1]);
        }
    }
    return act && (ks == 0);
}

// exp epilogue for non-clustered single-block fast_attention
template <int NJW>
__device__ __forceinline__ void epi_exp(bool own, u64 (&a)[4], int j,
                                        const float* __restrict__ bias,
                                        u64* xh, float* red, float* sinv) {
    const int w = threadIdx.x >> 5, lane = threadIdx.x & 31;
    if (own) {
        float4 bv = __ldg((const float4*)(bias + j));
        float bq[4] = {bv.x, bv.y, bv.z, bv.w};
        float sl = 0.f, sh2 = 0.f;
        #pragma unroll
        for (int q = 0; q < 4; q++) {
            float lo = __expf(lohi(a[q], 0) + bq[q]);
            float hi = __expf(lohi(a[q], 1) + bq[q]);
            xh[j + q] = packf2(lo, hi);
            sl += lo; sh2 += hi;
        }
        #pragma unroll
        for (int o = 16; o; o >>= 1) {
            sl += __shfl_xor_sync(0xffffffffu, sl, o);
            sh2 += __shfl_xor_sync(0xffffffffu, sh2, o);
        }
        if (lane == 0) { red[w * 2] = sl; red[w * 2 + 1] = sh2; }
    }
    __syncthreads();
    if (threadIdx.x < 2) {
        float s = 0.f;
        #pragma unroll
        for (int h = 0; h < NJW; h++) s += red[h * 2 + (int)threadIdx.x];
        sinv[threadIdx.x] = 1.f / s;
    }
    __syncthreads();
}

// ================= K0: fa_r only, 4-CTA cluster per row pair (j-split) ==============
__global__ void __launch_bounds__(1024, 1) __cluster_dims__(4, 1, 1) k0(
    const float* __restrict__ inputs,
    const float* __restrict__ r_w1, const float* __restrict__ r_b1,
    const float* __restrict__ r_w2, const float* __restrict__ r_b2) {
    extern __shared__ u64 sh[];
    u64* X = sh;                     // 512 packed input pair
    u64* H = sh + 512;               // 512 exp values (full after broadcast)
    u64* part = sh + 1024;           // 3968
    float* ps = (float*)(sh + 4992);    // 8 floats
    float* sinv = (float*)(sh + 4996);  // 2 floats

    const int tid = threadIdx.x, lane = tid & 31;
    uint32_t rank;
    asm("mov.u32 %0, %%cluster_ctarank;" : "=r"(rank));
    const int r0 = (blockIdx.x >> 2) * 2;

    if (blockIdx.x == 0) {
        if (tid < 48) g_s.pack[tid] = 0ull;
        if (tid < 24) g_flag[tid] = 0u;
    }
    if (tid < 512)
        X[tid] = packf2(__ldg(inputs + r0 * 512 + tid),
                        __ldg(inputs + (r0 + 1) * 512 + tid));

    u64 a[4]; int j;
    // GEMM1: exp(x @ r_w1 + b1) -> H (broadcast to all 4 CTAs)
    bool own = bgemm<1, 32, 512, 512, 8>(X, r_w1 + rank * 128, a, part, j);
    if (own) {
        int gj = rank * 128 + j;
        float4 bv = __ldg((const float4*)(r_b1 + gj));
        float bq[4] = {bv.x, bv.y, bv.z, bv.w};
        float sl = 0.f, sh2 = 0.f;
        #pragma unroll
        for (int q = 0; q < 4; q++) {
            float lo = __expf(lohi(a[q], 0) + bq[q]);
            float hi = __expf(lohi(a[q], 1) + bq[q]);
            u64 v = packf2(lo, hi);
            H[gj + q] = v;
            #pragma unroll
            for (uint32_t pr = 0; pr < 4; pr++)
                if (pr != rank) dsmem_st64(smem_u32(&H[gj + q]), pr, v);
            sl += lo; sh2 += hi;
        }
        #pragma unroll
        for (int o = 16; o; o >>= 1) {
            sl += __shfl_xor_sync(0xffffffffu, sl, o);
            sh2 += __shfl_xor_sync(0xffffffffu, sh2, o);
        }
        if (lane == 0) {
            ps[rank * 2] = sl; ps[rank * 2 + 1] = sh2;
            #pragma unroll
            for (uint32_t pr = 0; pr < 4; pr++)
                if (pr != rank) {
                    dsmem_stf(smem_u32(&ps[rank * 2]), pr, sl);
                    dsmem_stf(smem_u32(&ps[rank * 2 + 1]), pr, sh2);
                }
        }
    }
    CLUSTER_SYNC();
    if (tid < 2)
        sinv[tid] = 1.f / (ps[tid] + ps[2 + tid] + ps[4 + tid] + ps[6 + tid]);

    // GEMM2: yr = x * (softmax @ r_w2 + b2)  (own 128 cols, straight to global)
    own = bgemm<1, 32, 512, 512, 8>(H, r_w2 + rank * 128, a, part, j);
    if (own) {
        int gj = rank * 128 + j;
        float4 bv = __ldg((const float4*)(r_b2 + gj));
        float bq[4] = {bv.x, bv.y, bv.z, bv.w};
        #pragma unroll
        for (int q = 0; q < 4; q++) {
            float vlo = lohi(a[q], 0) * sinv[0] + bq[q];
            float vhi = lohi(a[q], 1) * sinv[1] + bq[q];
            u64 xv = X[gj + q];
            g_s.yr[r0 * 512 + gj + q] = lohi(xv, 0) * vlo;
            g_s.yr[(r0 + 1) * 512 + gj + q] = lohi(xv, 1) * vhi;
        }
    }
    CLUSTER_SYNC();
}

// ================= K1: read GEMM tiles (blocks 8..) + fa_u/updw (blocks 0-7) ========
__global__ void __launch_bounds__(512, 1) k1(const float* __restrict__ W,
                                             const float* __restrict__ bias,
                                             const float* __restrict__ inputs,
                                             const float* __restrict__ u_w1,
                                             const float* __restrict__ u_b1,
                                             const float* __restrict__ u_w2,
                                             const float* __restrict__ u_b2,
                                             const float* __restrict__ W_uw,
                                             const float* __restrict__ b_uw) {
    extern __shared__ u64 shr[];
    const int tid = threadIdx.x, bx = blockIdx.x;
    const int NB = gridDim.x;

    if (bx < 8) {
        // ---- fa_u role: one row pair per block, full 512 cols, then updw ----
        u64* X = shr;                // 512
        u64* H = shr + 512;          // 512
        u64* Y = shr + 1024;         // 512
        u64* part = shr + 1536;      // 1536
        float* red = (float*)(shr + 3072);   // 8 floats
        float* sinv = (float*)(shr + 3076);  // 2 floats
        const int r0 = bx * 2;

        if (tid < 512)
            X[tid] = packf2(__ldg(inputs + r0 * 512 + tid),
                            __ldg(inputs + (r0 + 1) * 512 + tid));
        u64 a[4]; int j;
        bool own = bgemm<4, 4, 512, 512, 8>(X, u_w1, a, part, j);
        epi_exp<4>(own, a, j, u_b1, H, red, sinv);
        own = bgemm<4, 4, 512, 512, 8>(H, u_w2, a, part, j);
        if (own) {
            float4 bv = __ldg((const float4*)(u_b2 + j));
            float bq[4] = {bv.x, bv.y, bv.z, bv.w};
            #pragma unroll
            for (int q = 0; q < 4; q++) {
                float vlo = lohi(a[q], 0) * sinv[0] + bq[q];
                float vhi = lohi(a[q], 1) * sinv[1] + bq[q];
                u64 xv = X[j + q];
                Y[j + q] = packf2(lohi(xv, 0) * vlo, lohi(xv, 1) * vhi);
            }
        }
        __syncthreads();
        const int w = tid >> 5, lane = tid & 31;
        if (w < 3) {
            u64 acc = 0ull;
            for (int k = lane; k < 512; k += 32)
                ffma2(acc, Y[k], pack2(__ldg(W_uw + k * 3 + w)));
            #pragma unroll
            for (int o = 16; o; o >>= 1)
                acc = addf2(acc, __shfl_xor_sync(0xffffffffu, acc, o));
            if (lane == 0) {
                float bb = __ldg(b_uw + w);
                g_s.updw[r0 * 3 + w] = 1.f / (1.f + __expf(-(lohi(acc, 0) + bb)));
                g_s.updw[(r0 + 1) * 3 + w] = 1.f / (1.f + __expf(-(lohi(acc, 1) + bb)));
            }
        }
        return;
    }

    // ---- read-tile role ----
    u64* xs2 = shr;
    u64* part = shr + 4096;
    const int bx2 = bx - 8;
    const int NB2 = NB - 8;

    for (int idx = tid; idx < 4096; idx += 512) {
        int p = idx / 512, k = idx - p * 512;
        float lo = __ldcg(g_s.yr + (2 * p) * 512 + k);
        float hi = __ldcg(g_s.yr + (2 * p + 1) * 512 + k);
        xs2[k * 8 + p] = packf2(lo, hi);
    }
    __syncthreads();

    const int w = tid >> 5, lane = tid & 31;
    const int ts = w >> 2, kh = w & 3;
    const int base = 471 / NB2, rem = 471 - base * NB2;
    const int cnt = base + (bx2 < rem ? 1 : 0);
    const int start = bx2 * base + (bx2 < rem ? bx2 : rem);
    const bool act = ts < cnt;

    int isec = 0, j0 = 0, j1 = 0;
    long n0 = 0;
    bool v0 = false;
    u64 a0[8], a1[8];

    if (act) {
        int gtile = start + ts;
        isec = gtile / 157;
        int t = gtile - isec * 157;
        j0 = t * 64 + lane * 2; j1 = j0 + 1;
        v0 = j0 < 10000;
        n0 = (long)isec * 10000 + j0;
        #pragma unroll
        for (int p = 0; p < 8; p++) { a0[p] = 0ull; a1[p] = 0ull; }

        const float* W0 = W + (long)(kh * 128) * 30000;
        const u64* xk = xs2 + (kh * 128) * 8;
        #pragma unroll 1
        for (int it = 0; it < 128; it += 8) {
            float2 wv[8];
            #pragma unroll
            for (int u = 0; u < 8; u++)
                wv[u] = v0 ? __ldg((const float2*)(W0 + (long)u * 30000 + n0))
                           : make_float2(0.f, 0.f);
            #pragma unroll
            for (int u = 0; u < 8; u++) {
                u64 wa2 = pack2(wv[u].x), wb2 = pack2(wv[u].y);
                const u64* xp = xk + u * 8;
                #pragma unroll
                for (int p = 0; p < 8; p++) {
                    u64 xv = xp[p];
                    ffma2(a0[p], xv, wa2);
                    ffma2(a1[p], xv, wb2);
                }
            }
            W0 += 8L * 30000; xk += 64;
        }
        if (kh > 0) {
            u64* ps = part + ((ts * 3 + (kh - 1)) * 32 + lane) * 16;
            #pragma unroll
            for (int p = 0; p < 8; p++) { ps[p] = a0[p]; ps[8 + p] = a1[p]; }
        }
    }
    __syncthreads();

    if (act && kh == 0) {
        #pragma unroll
        for (int h = 0; h < 3; h++) {
            const u64* ps = part + ((ts * 3 + h) * 32 + lane) * 16;
            #pragma unroll
            for (int p = 0; p < 8; p++) {
                a0[p] = addf2(a0[p], ps[p]);
                a1[p] = addf2(a1[p], ps[8 + p]);
            }
        }
        float2 bv = v0 ? __ldg((const float2*)(bias + n0)) : make_float2(0.f, 0.f);
        #pragma unroll
        for (int b = 0; b < 16; b++) {
            float z0 = lohi(a0[b >> 1], b & 1) + bv.x;
            float z1 = lohi(a1[b >> 1], b & 1) + bv.y;
            u64 c0 = v0 ? (((u64)forder(z0) << 32) | (u64)(0xFFFFFFFFu - (unsigned)j0)) : 0ull;
            u64 c1 = v0 ? (((u64)forder(z1) << 32) | (u64)(0xFFFFFFFFu - (unsigned)j1)) : 0ull;
            u64 c = c0 > c1 ? c0 : c1;
            #pragma unroll
            for (int o = 16; o; o >>= 1) {
                u64 q = __shfl_xor_sync(0xffffffffu, c, o);
                if (q > c) c = q;
            }
            if (lane == 0) atomicMax(&g_s.pack[b * 3 + isec], c);
        }
    }
}

// ---------------- k2 role: fa_um + r-update for task t (sub-pair inside cluster) ----
__device__ void k2_role(u64* sh, int t, uint32_t rank,
                        const float* __restrict__ inputs, const float* __restrict__ memory,
                        const float* __restrict__ um_w1, const float* __restrict__ um_b1,
                        const float* __restrict__ um_w2, const float* __restrict__ um_b2,
                        const float* __restrict__ W_um, const float* __restrict__ b_um) {
    u64* cat = sh;                   // 768
    u64* e = sh + 768;               // 768
    u64* yv = sh + 1536;             // 768
    u64* part = sh + 2304;           // 2944
    float* red = (float*)(sh + 5248);   // 6
    float* ps = (float*)(sh + 5251);    // 4
    float* sinv = (float*)(sh + 5253);  // 2
    __shared__ long rowoff[2];
    __shared__ float su[2];

    const int tid = threadIdx.x;
    const uint32_t sr = rank & 1u;
    const uint32_t peer = rank ^ 1u;
    const int i = t >> 3;
    const int r0 = (t & 7) * 2;

    if (tid < 2) {
        u64 p = __ldcg(&g_s.pack[(r0 + tid) * 3 + i]);
        unsigned idx = 0xFFFFFFFFu - (unsigned)(p & 0xFFFFFFFFull);
        rowoff[tid] = ((long)(r0 + tid) * 10000 + idx) * 256;
        su[tid] = __ldcg(&g_s.updw[(r0 + tid) * 3 + i]);
    }
    __syncthreads();
    if (tid < 768) {
        float lo, hi;
        if (tid < 256) {
            lo = __ldg(memory + rowoff[0] + tid);
            hi = __ldg(memory + rowoff[1] + tid);
        } else {
            lo = __ldg(inputs + r0 * 512 + (tid - 256));
            hi = __ldg(inputs + (r0 + 1) * 512 + (tid - 256));
        }
        cat[tid] = packf2(lo, hi);
    }

    u64 a[4]; int j;
    bool own = bgemm<3, 8, 768, 768, 8>(cat, um_w1 + sr * 384, a, part, j);
    {
        const int w = tid >> 5, lane = tid & 31;
        if (own) {
            int gj = sr * 384 + j;
            float4 bv = __ldg((const float4*)(um_b1 + gj));
            float bq[4] = {bv.x, bv.y, bv.z, bv.w};
            float sl = 0.f, sh2 = 0.f;
            #pragma unroll
            for (int q = 0; q < 4; q++) {
                float lo = __expf(lohi(a[q], 0) + bq[q]);
                float hi = __expf(lohi(a[q], 1) + bq[q]);
                u64 v = packf2(lo, hi);
                e[gj + q] = v;
                dsmem_st64(smem_u32(&e[gj + q]), peer, v);
                sl += lo; sh2 += hi;
            }
            #pragma unroll
            for (int o = 16; o; o >>= 1) {
                sl += __shfl_xor_sync(0xffffffffu, sl, o);
                sh2 += __shfl_xor_sync(0xffffffffu, sh2, o);
            }
            if (lane == 0) { red[w * 2] = sl; red[w * 2 + 1] = sh2; }
        }
        __syncthreads();
        if (tid < 2) {
            float s = red[tid] + red[2 + tid] + red[4 + tid];
            ps[sr * 2 + tid] = s;
            dsmem_stf(smem_u32(&ps[sr * 2 + tid]), peer, s);
        }
    }
    CLUSTER_SYNC();
    if (tid < 2) sinv[tid] = 1.f / (ps[tid] + ps[2 + tid]);

    own = bgemm<3, 8, 768, 768, 8>(e, um_w2 + sr * 384, a, part, j);
    if (own) {
        int gj = sr * 384 + j;
        float4 bv = __ldg((const float4*)(um_b2 + gj));
        float bq[4] = {bv.x, bv.y, bv.z, bv.w};
        #pragma unroll
        for (int q = 0; q < 4; q++) {
            float vlo = lohi(a[q], 0) * sinv[0] + bq[q];
            float vhi = lohi(a[q], 1) * sinv[1] + bq[q];
            u64 cv = cat[gj + q];
            u64 y = packf2(lohi(cv, 0) * vlo, lohi(cv, 1) * vhi);
            yv[gj + q] = y;
            dsmem_st64(smem_u32(&yv[gj + q]), peer, y);
        }
    }
    CLUSTER_SYNC();

    own = bgemm<1, 24, 768, 256, 8>(yv, W_um + sr * 128, a, part, j);
    if (own) {
        int gj = sr * 128 + j;
        float4 bv = __ldg((const float4*)(b_um + gj));
        float bq[4] = {bv.x, bv.y, bv.z, bv.w};
        float ulo = su[0], uhi = su[1];
        #pragma unroll
        for (int q = 0; q < 4; q++) {
            float vlo = fmaxf(lohi(a[q], 0) + bq[q], 0.f);
            float vhi = fmaxf(lohi(a[q], 1) + bq[q], 0.f);
            u64 rv = cat[gj + q];
            g_s.rc[i][r0 * 256 + gj + q] = ulo * vlo + (1.f - ulo) * lohi(rv, 0);
            g_s.rc[i][(r0 + 1) * 256 + gj + q] = uhi * vhi + (1.f - uhi) * lohi(rv, 1);
        }
    }
    __syncthreads();
    if (tid == 0) {
        __threadfence();
        atomicAdd((unsigned*)&g_flag[i * 8 + (t & 7)], 1u);
    }
}

// ---------------- k3 role: recurrent loop, 2 rows per 4-CTA cluster -----------------
__device__ void k3_role(u64* sh, int pair, uint32_t rank,
                        const float* __restrict__ am_w1, const float* __restrict__ am_b1,
                        const float* __restrict__ am_w2, const float* __restrict__ am_b2,
                        const float* __restrict__ W_am, const float* __restrict__ b_am,
                        float* __restrict__ out) {
    u64* A = sh;                     // 512: [rc(256) | m(256)]
    u64* B = sh + 512;               // 512
    u64* C = sh + 1024;              // 512
    u64* part = sh + 1536;           // 3968
    float* ps = (float*)(sh + 5504);    // 8
    float* sinv = (float*)(sh + 5508);  // 2
    __shared__ float srw[6];

    const int tid = threadIdx.x, lane = tid & 31;
    const int r0 = pair * 2;

    if (tid < 6) {
        int rr = tid / 3, ii = tid - rr * 3;
        u64 p = __ldcg(&g_s.pack[(r0 + rr) * 3 + ii]);
        srw[tid] = tanhf(forder_inv((unsigned)(p >> 32)));
    }
    if (tid >= 256 && tid < 512) A[tid] = 0ull;   // m = 0

    u64 a[4]; u64 a2[2]; int j;
    for (int i = 0; i < 3; i++) {
        if (tid == 0) {
            while (g_flag[i * 8 + pair] < 2u) { }
            __threadfence();
        }
        __syncthreads();
        if (tid < 256)
            A[tid] = packf2(__ldcg(g_s.rc[i] + r0 * 256 + tid),
                            __ldcg(g_s.rc[i] + (r0 + 1) * 256 + tid));
        // GEMM1: exp(A @ am_w1) -> B (broadcast)
        bool own = bgemm<1, 32, 512, 512, 8>(A, am_w1 + rank * 128, a, part, j);
        if (own) {
            int gj = rank * 128 + j;
            float4 bv = __ldg((const float4*)(am_b1 + gj));
            float bq[4] = {bv.x, bv.y, bv.z, bv.w};
            float sl = 0.f, sh2 = 0.f;
            #pragma unroll
            for (int q = 0; q < 4; q++) {
                float lo = __expf(lohi(a[q], 0) + bq[q]);
                float hi = __expf(lohi(a[q], 1) + bq[q]);
                u64 v = packf2(lo, hi);
                B[gj + q] = v;
                #pragma unroll
                for (uint32_t pr = 0; pr < 4; pr++)
                    if (pr != rank) dsmem_st64(smem_u32(&B[gj + q]), pr, v);
                sl += lo; sh2 += hi;
            }
            #pragma unroll
            for (int o = 16; o; o >>= 1) {
                sl += __shfl_xor_sync(0xffffffffu, sl, o);
                sh2 += __shfl_xor_sync(0xffffffffu, sh2, o);
            }
            if (lane == 0) {
                ps[rank * 2] = sl; ps[rank * 2 + 1] = sh2;
                #pragma unroll
                for (uint32_t pr = 0; pr < 4; pr++)
                    if (pr != rank) {
                        dsmem_stf(smem_u32(&ps[rank * 2]), pr, sl);
                        dsmem_stf(smem_u32(&ps[rank * 2 + 1]), pr, sh2);
                    }
            }
        }
        CLUSTER_SYNC();
        if (tid < 2)
            sinv[tid] = 1.f / (ps[tid] + ps[2 + tid] + ps[4 + tid] + ps[6 + tid]);
        // GEMM2: y = A * (softmax @ am_w2 + b) -> C (broadcast)
        own = bgemm<1, 32, 512, 512, 8>(B, am_w2 + rank * 128, a, part, j);
        if (own) {
            int gj = rank * 128 + j;
            float4 bv = __ldg((const float4*)(am_b2 + gj));
            float bq[4] = {bv.x, bv.y, bv.z, bv.w};
            #pragma unroll
            for (int q = 0; q < 4; q++) {
                float vlo = lohi(a[q], 0) * sinv[0] + bq[q];
                float vhi = lohi(a[q], 1) * sinv[1] + bq[q];
                u64 cv = A[gj + q];
                u64 y = packf2(lohi(cv, 0) * vlo, lohi(cv, 1) * vhi);
                C[gj + q] = y;
                #pragma unroll
                for (uint32_t pr = 0; pr < 4; pr++)
                    if (pr != rank) dsmem_st64(smem_u32(&C[gj + q]), pr, y);
            }
        }
        CLUSTER_SYNC();
        // GEMM3: m = rw * relu(C @ W_am + b) -> A[256+] (broadcast)
        bool own2 = bgemm2<32, 512, 256, 8>(C, W_am + rank * 64, a2, part, j);
        if (own2) {
            int gj = rank * 64 + j;
            float2 bv = __ldg((const float2*)(b_am + gj));
            float rwlo = srw[i], rwhi = srw[3 + i];
            float bq[2] = {bv.x, bv.y};
            #pragma unroll
            for (int q = 0; q < 2; q++) {
                float mlo = rwlo * fmaxf(lohi(a2[q], 0) + bq[q], 0.f);
                float mhi = rwhi * fmaxf(lohi(a2[q], 1) + bq[q], 0.f);
                u64 mv = packf2(mlo, mhi);
                A[256 + gj + q] = mv;
                #pragma unroll
                for (uint32_t pr = 0; pr < 4; pr++)
                    if (pr != rank) dsmem_st64(smem_u32(&A[256 + gj + q]), pr, mv);
                if (i == 2) {
                    out[r0 * 256 + gj + q] = tanhf(mlo);
                    out[(r0 + 1) * 256 + gj + q] = tanhf(mhi);
                }
            }
        }
        CLUSTER_SYNC();
    }
}

// ================= K23: fused k2 (producer) + k3 (consumer) =================
__global__ void __launch_bounds__(1024, 1) __cluster_dims__(4, 1, 1) k23(
    const float* __restrict__ inputs, const float* __restrict__ memory,
    const float* __restrict__ um_w1, const float* __restrict__ um_b1,
    const float* __restrict__ um_w2, const float* __restrict__ um_b2,
    const float* __restrict__ W_um, const float* __restrict__ b_um,
    const float* __restrict__ am_w1, const float* __restrict__ am_b1,
    const float* __restrict__ am_w2, const float* __restrict__ am_b2,
    const float* __restrict__ W_am, const float* __restrict__ b_am,
    float* __restrict__ out) {
    extern __shared__ u64 sh[];
    const int cid = blockIdx.x >> 2;
    uint32_t rank;
    asm("mov.u32 %0, %%cluster_ctarank;" : "=r"(rank));
    if (cid < 12) {
        int t = cid * 2 + (int)(rank >> 1);   // i-major: t = i*8 + pair
        k2_role(sh, t, rank, inputs, memory, um_w1, um_b1, um_w2, um_b2, W_um, b_um);
    } else {
        k3_role(sh, cid - 12, rank, am_w1, am_b1, am_w2, am_b2, W_am, b_am, out);
    }
}

// ---------------- host launcher ----------------
extern "C" void kernel_launch(void* const* d_in, const int* in_sizes, int n_in,
                              void* d_out, int out_size) {
    const float* inputs = (const float*)d_in[0];
    const float* memory = (const float*)d_in[1];
    const float* r_w1 = (const float*)d_in[2];
    const float* r_b1 = (const float*)d_in[3];
    const float* r_w2 = (const float*)d_in[4];
    const float* r_b2 = (const float*)d_in[5];
    const float* W_read = (const float*)d_in[6];
    const float* b_read = (const float*)d_in[7];
    const float* u_w1 = (const float*)d_in[8];
    const float* u_b1 = (const float*)d_in[9];
    const float* u_w2 = (const float*)d_in[10];
    const float* u_b2 = (const float*)d_in[11];
    const float* W_uw = (const float*)d_in[12];
    const float* b_uw = (const float*)d_in[13];
    const float* um_w1 = (const float*)d_in[14];
    const float* um_b1 = (const float*)d_in[15];
    const float* um_w2 = (const float*)d_in[16];
    const float* um_b2 = (const float*)d_in[17];
    const float* W_um = (const float*)d_in[18];
    const float* b_um = (const float*)d_in[19];
    const float* am_w1 = (const float*)d_in[20];
    const float* am_b1 = (const float*)d_in[21];
    const float* am_w2 = (const float*)d_in[22];
    const float* am_b2 = (const float*)d_in[23];
    const float* W_am = (const float*)d_in[24];
    const float* b_am = (const float*)d_in[25];
    float* out = (float*)d_out;

    static int NB = 0;
    if (NB == 0) {
        cudaDeviceGetAttribute(&NB, cudaDevAttrMultiProcessorCount, 0);
        if (NB <= 0) NB = 148;
    }
    const int DSM0 = 39984;   // k0: 4998 u64
    const int DSM1 = 81920;   // k1
    const int DSM23 = 44080;  // k23: max(k2 5254, k3 5509) u64
    static bool attr_set = false;
    if (!attr_set) {
        cudaFuncSetAttribute(k0,  cudaFuncAttributeMaxDynamicSharedMemorySize, DSM0);
        cudaFuncSetAttribute(k1,  cudaFuncAttributeMaxDynamicSharedMemorySize, DSM1);
        cudaFuncSetAttribute(k23, cudaFuncAttributeMaxDynamicSharedMemorySize, DSM23);
        attr_set = true;
    }

    k0<<<32, 1024, DSM0>>>(inputs, r_w1, r_b1, r_w2, r_b2);
    k1<<<NB, 512, DSM1>>>(W_read, b_read, inputs, u_w1, u_b1, u_w2, u_b2, W_uw, b_uw);
    k23<<<80, 1024, DSM23>>>(inputs, memory, um_w1, um_b1, um_w2, um_b2,
                             W_um, b_um, am_w1, am_b1, am_w2, am_b2,
                             W_am, b_am, out);
}